// round 13
// baseline (speedup 1.0000x reference)
#include <cuda_runtime.h>
#include <cstdint>

#define NN 65536
#define NE (NN*16)
#define NG 128
#define PN 512
#define HIDD 128
#define INDIM 64
#define BN_EPS 1e-5f

__device__ __forceinline__ uint32_t f2tf32(float f){
  uint32_t u; asm("cvt.rna.tf32.f32 %0, %1;" : "=r"(u) : "f"(f)); return u;
}
__device__ __forceinline__ void mma_tf32(float& c0, float& c1, float& c2, float& c3,
                                         uint32_t a0, uint32_t a1, uint32_t a2, uint32_t a3,
                                         uint32_t b0, uint32_t b1){
  asm volatile("mma.sync.aligned.m16n8k8.row.col.f32.tf32.tf32.f32 "
               "{%0,%1,%2,%3}, {%4,%5,%6,%7}, {%8,%9}, {%0,%1,%2,%3};"
               : "+f"(c0), "+f"(c1), "+f"(c2), "+f"(c3)
               : "r"(a0), "r"(a1), "r"(a2), "r"(a3), "r"(b0), "r"(b1));
}
__device__ __forceinline__ uint4 q4(float4 v){
  return make_uint4(f2tf32(v.x), f2tf32(v.y), f2tf32(v.z), f2tf32(v.w));
}
__device__ __forceinline__ void cp16(uint32_t* dst, const uint32_t* src){
  uint32_t d = (uint32_t)__cvta_generic_to_shared(dst);
  asm volatile("cp.async.cg.shared.global [%0], [%1], 16;" :: "r"(d), "l"(src));
}
#define CP_COMMIT() asm volatile("cp.async.commit_group;" ::: "memory")

// ================= scratch =================
__device__ int    g_count[NN];
__device__ int    g_rowptr[NN+1];
__device__ int    g_cursor[NN];
__device__ int    g_part[256];
__device__ float2 g_edge[NE];     // (src bits, weight)
__device__ float  g_dis[NN];
__device__ float  g_selfn[NN];
__device__ float  g_h[(size_t)NN*HIDD];
__device__ float  g_h2[(size_t)NN*HIDD];
__device__ float  g_qkv[(size_t)NN*3*HIDD];
__device__ float  g_attno[(size_t)NN*HIDD];
__device__ uint32_t g_wr[122880];   // pre-rounded weights: W0|Wh|aiw|aow

// ================= weight pre-round (tf32) =================
__global__ void roundw_kernel(const float* __restrict__ W0, const float* __restrict__ Wh,
                              const float* __restrict__ aiw, const float* __restrict__ aow){
  int i = (blockIdx.x*256 + threadIdx.x)*4;
  float4 v;
  if(i < 8192)        v = *(const float4*)(W0 + i);
  else if(i < 57344)  v = *(const float4*)(Wh + (i - 8192));
  else if(i < 106496) v = *(const float4*)(aiw + (i - 57344));
  else                v = *(const float4*)(aow + (i - 106496));
  *(uint4*)(g_wr + i) = q4(v);
}

// ================= CSR build =================
__global__ void count_kernel(const int* __restrict__ dst){
  int e = blockIdx.x*blockDim.x + threadIdx.x;
  if(e < NE) atomicAdd(&g_count[dst[e]], 1);
}
__global__ void scan1_kernel(){
  __shared__ int wsum[8];
  int b = blockIdx.x, t = threadIdx.x;
  int i = b*256 + t;
  int c = g_count[i];
  float dis = rsqrtf((float)(c + 1));
  g_dis[i] = dis;
  g_selfn[i] = dis*dis;
  int lane = t & 31, w = t >> 5;
  int v = c;
  #pragma unroll
  for(int o=1;o<32;o<<=1){ int u=__shfl_up_sync(0xffffffffu,v,o); if(lane>=o) v+=u; }
  if(lane==31) wsum[w]=v;
  __syncthreads();
  if(w==0){
    int s = (lane<8)? wsum[lane] : 0;
    #pragma unroll
    for(int o=1;o<8;o<<=1){ int u=__shfl_up_sync(0xffffffffu,s,o); if(lane>=o) s+=u; }
    if(lane<8) wsum[lane]=s;
  }
  __syncthreads();
  int excl = v - c + (w ? wsum[w-1] : 0);
  g_rowptr[i] = excl;
  if(t==255) g_part[b] = excl + c;
}
// merged scan2+scan3: each block redundantly reduces partials below its id
__global__ void scan23_kernel(){
  __shared__ int red[8];
  int b = blockIdx.x, t = threadIdx.x;
  int lane = t & 31, w = t >> 5;
  int v = (t < b) ? g_part[t] : 0;
  #pragma unroll
  for(int o=16;o;o>>=1) v += __shfl_xor_sync(0xffffffffu, v, o);
  if(lane == 0) red[w] = v;
  __syncthreads();
  if(w == 0){
    int s = (lane < 8) ? red[lane] : 0;
    #pragma unroll
    for(int o=4;o;o>>=1) s += __shfl_xor_sync(0xffffffffu, s, o);
    if(lane == 0) red[0] = s;
  }
  __syncthreads();
  int poff = red[0];
  int i = b*256 + t;
  int r = g_rowptr[i] + poff;
  g_rowptr[i] = r;
  g_cursor[i] = r;
  if(i == 0) g_rowptr[NN] = NE;
}
__global__ void fill_kernel(const int* __restrict__ src, const int* __restrict__ dst){
  int e = blockIdx.x*blockDim.x + threadIdx.x;
  if(e >= NE) return;
  int s = src[e], d = dst[e];
  int pos = atomicAdd(&g_cursor[d], 1);
  g_edge[pos] = make_float2(__int_as_float(s), g_dis[s]*g_dis[d]);
}

// ====== fused aggregate + tf32 GEMM + BN + ReLU (per GCN layer) ======
// CTA: 128 rows; gathers A rows from hin (prev-layer buffer) straight into smem,
// B (pre-rounded W [KK][128]) cp.async double-buffered. Output tf32-rounded to hout.
template<int KK>
__global__ __launch_bounds__(256, 2)
void agggemm_kernel(const float* __restrict__ hin, const uint32_t* __restrict__ B,
                    const float* __restrict__ bias,
                    const float* __restrict__ bng, const float* __restrict__ bnb,
                    const float* __restrict__ bnm, const float* __restrict__ bnv,
                    float* __restrict__ hout)
{
  constexpr int SA  = (KK == 128) ? 132 : 68;  // A row stride (u32)
  constexpr int CK  = 32;
  constexpr int NCH = KK / CK;
  constexpr int SBN = 132;
  constexpr int ABUF = 128*SA;
  constexpr int BBUF = 32*SBN;     // 4224 u32 per chunk buffer
  extern __shared__ uint32_t sm[];
  uint32_t* As = sm;
  uint32_t* Bb = sm + ABUF;        // two chunk buffers
  const int tid = threadIdx.x;
  const int lane = tid & 31, wid = tid >> 5;
  const int row0 = blockIdx.x * 128;

  auto stageB = [&](int ch){
    uint32_t* Bs = Bb + (ch & 1)*BBUF;
    const int kbase = ch*CK;
    #pragma unroll
    for(int i = 0; i < 4; i++){
      int idx = tid + i*256;
      int k = idx >> 5, n4 = idx & 31;
      cp16(Bs + k*SBN + n4*4, B + (size_t)(kbase + k)*HIDD + n4*4);
    }
    CP_COMMIT();
  };

  stageB(0);
  if(NCH > 1) stageB(1);

  // ---- gather phase: warp w owns rows w*16 .. w*16+15 ----
  for(int i = 0; i < 16; i++){
    int r = wid*16 + i;
    int node = row0 + r;
    if(KK == 128){
      float4 a = *((const float4*)(hin + (size_t)node*KK) + lane);
      float sn = g_selfn[node];
      a.x *= sn; a.y *= sn; a.z *= sn; a.w *= sn;
      int beg = g_rowptr[node], end = g_rowptr[node+1];
      for(int b = beg; b < end; b += 32){
        int m = min(32, end - b);
        float2 ed = make_float2(0.f, 0.f);
        if(lane < m) ed = g_edge[b + lane];
        #pragma unroll 4
        for(int j = 0; j < m; j++){
          int   s = __shfl_sync(0xffffffffu, __float_as_int(ed.x), j);
          float w = __shfl_sync(0xffffffffu, ed.y, j);
          float4 v = *((const float4*)(hin + (size_t)s*KK) + lane);
          a.x += w*v.x; a.y += w*v.y; a.z += w*v.z; a.w += w*v.w;
        }
      }
      *(uint4*)(As + r*SA + lane*4) = q4(a);
    } else {
      float2 a = *((const float2*)(hin + (size_t)node*KK) + lane);
      float sn = g_selfn[node];
      a.x *= sn; a.y *= sn;
      int beg = g_rowptr[node], end = g_rowptr[node+1];
      for(int b = beg; b < end; b += 32){
        int m = min(32, end - b);
        float2 ed = make_float2(0.f, 0.f);
        if(lane < m) ed = g_edge[b + lane];
        #pragma unroll 4
        for(int j = 0; j < m; j++){
          int   s = __shfl_sync(0xffffffffu, __float_as_int(ed.x), j);
          float w = __shfl_sync(0xffffffffu, ed.y, j);
          float2 v = *((const float2*)(hin + (size_t)s*KK) + lane);
          a.x += w*v.x; a.y += w*v.y;
        }
      }
      *(uint2*)(As + r*SA + lane*2) = make_uint2(f2tf32(a.x), f2tf32(a.y));
    }
  }
  __syncthreads();

  // ---- MMA mainloop ----
  const int m0 = (wid >> 1) * 32;
  const int n0 = (wid & 1) * 64;
  const int g  = lane >> 2;
  const int t4 = lane & 3;

  float acc[2][8][4];
  #pragma unroll
  for(int i=0;i<2;i++)
    #pragma unroll
    for(int j=0;j<8;j++)
      #pragma unroll
      for(int q=0;q<4;q++) acc[i][j][q]=0.f;

  const uint32_t* Aw0 = As + (m0 + g)*SA + t4;
  const uint32_t* Aw1 = As + (m0 + 16 + g)*SA + t4;

  #pragma unroll 1
  for(int ch = 0; ch < NCH; ch++){
    if(ch + 1 < NCH) asm volatile("cp.async.wait_group 1;" ::: "memory");
    else             asm volatile("cp.async.wait_group 0;" ::: "memory");
    __syncthreads();

    const uint32_t* Bs = Bb + (ch & 1)*BBUF;
    const uint32_t* Bw0 = Bs + t4*SBN + n0 + g;
    const int kbase = ch*CK;

    #pragma unroll 1
    for(int ks = 0; ks < CK/8; ks++){
      const int k0 = kbase + ks*8;
      const int kl = ks*8;
      uint32_t af[2][4];
      af[0][0] = Aw0[k0];       af[0][1] = Aw0[8*SA + k0];
      af[0][2] = Aw0[k0 + 4];   af[0][3] = Aw0[8*SA + k0 + 4];
      af[1][0] = Aw1[k0];       af[1][1] = Aw1[8*SA + k0];
      af[1][2] = Aw1[k0 + 4];   af[1][3] = Aw1[8*SA + k0 + 4];
      #pragma unroll
      for(int nj = 0; nj < 8; nj++){
        uint32_t b0 = Bw0[kl*SBN + nj*8];
        uint32_t b1 = Bw0[(kl+4)*SBN + nj*8];
        mma_tf32(acc[0][nj][0], acc[0][nj][1], acc[0][nj][2], acc[0][nj][3],
                 af[0][0], af[0][1], af[0][2], af[0][3], b0, b1);
        mma_tf32(acc[1][nj][0], acc[1][nj][1], acc[1][nj][2], acc[1][nj][3],
                 af[1][0], af[1][1], af[1][2], af[1][3], b0, b1);
      }
    }
    if(ch + 2 < NCH){
      __syncthreads();
      stageB(ch + 2);
    }
  }

  // ---- epilogue: bias + BN + ReLU, tf32-rounded ----
  #pragma unroll
  for(int mi = 0; mi < 2; mi++){
    #pragma unroll
    for(int nj = 0; nj < 8; nj++){
      int c = n0 + nj*8 + t4*2;
      float s0 = bng[c  ]*rsqrtf(bnv[c  ] + BN_EPS);
      float s1 = bng[c+1]*rsqrtf(bnv[c+1] + BN_EPS);
      #pragma unroll
      for(int h = 0; h < 2; h++){
        int r = row0 + m0 + mi*16 + g + h*8;
        float v0 = acc[mi][nj][h*2+0] + bias[c];
        float v1 = acc[mi][nj][h*2+1] + bias[c+1];
        v0 = fmaxf((v0 - bnm[c  ])*s0 + bnb[c  ], 0.f);
        v1 = fmaxf((v1 - bnm[c+1])*s1 + bnb[c+1], 0.f);
        *(uint2*)(hout + (size_t)r*HIDD + c) = make_uint2(f2tf32(v0), f2tf32(v1));
      }
    }
  }
}

// ========== tf32 mma.sync GEMM (BT=1): cp.async double-buffered, CK=32, 2 CTAs/SM ====
// A, B pre-rounded tf32 bits. RND=1: round outputs. POOL=1: fused mean pool.
template<int POOL, int RND>
__global__ __launch_bounds__(256, 2)
void gemm_mma_kernel(const float* __restrict__ A, const uint32_t* __restrict__ B,
                     const float* __restrict__ bias,
                     float* __restrict__ C, int Ndt, float* __restrict__ emb)
{
  constexpr int KK  = 128;
  constexpr int CK  = 32;
  constexpr int NCH = KK / CK;
  constexpr int SA  = 36;
  constexpr int BUFA = 128*SA;
  constexpr int BUF  = 2*BUFA;
  extern __shared__ uint32_t sm[];
  const int tid = threadIdx.x;
  const int lane = tid & 31, wid = tid >> 5;
  const int row0 = blockIdx.x * 128;
  const int col0 = blockIdx.y * 128;
  const uint32_t* Ag = (const uint32_t*)A;

  const int m0 = (wid >> 1) * 32;
  const int n0 = (wid & 1) * 64;
  const int g  = lane >> 2;
  const int t4 = lane & 3;

  float acc[2][8][4];
  #pragma unroll
  for(int i=0;i<2;i++)
    #pragma unroll
    for(int j=0;j<8;j++)
      #pragma unroll
      for(int q=0;q<4;q++) acc[i][j][q]=0.f;

  auto stage = [&](int ch){
    const int kbase = ch*CK;
    uint32_t* As = sm + (ch & 1)*BUF;
    uint32_t* Bs = As + BUFA;
    #pragma unroll
    for(int i = 0; i < 4; i++){
      int idx = tid + i*256;
      int r = idx >> 3, q = idx & 7;
      cp16(As + r*SA + q*4, Ag + (size_t)(row0 + r)*KK + kbase + q*4);
    }
    #pragma unroll
    for(int i = 0; i < 4; i++){
      int idx = tid + i*256;
      int r = idx >> 3, q = idx & 7;
      cp16(Bs + r*SA + q*4, B + (size_t)(col0 + r)*KK + kbase + q*4);
    }
    CP_COMMIT();
  };

  stage(0);

  #pragma unroll 1
  for(int ch = 0; ch < NCH; ch++){
    if(ch + 1 < NCH) stage(ch + 1);
    if(ch + 1 < NCH) asm volatile("cp.async.wait_group 1;" ::: "memory");
    else             asm volatile("cp.async.wait_group 0;" ::: "memory");
    __syncthreads();

    uint32_t* As = sm + (ch & 1)*BUF;
    uint32_t* Bs = As + BUFA;
    const uint32_t* Aw0 = As + (m0 + g)*SA + t4;
    const uint32_t* Aw1 = As + (m0 + 16 + g)*SA + t4;
    const uint32_t* Bw1 = Bs + (n0 + g)*SA + t4;

    #pragma unroll 1
    for(int ks = 0; ks < CK/8; ks++){
      const int k0 = ks*8;
      uint32_t af[2][4];
      af[0][0] = Aw0[k0];       af[0][1] = Aw0[8*SA + k0];
      af[0][2] = Aw0[k0 + 4];   af[0][3] = Aw0[8*SA + k0 + 4];
      af[1][0] = Aw1[k0];       af[1][1] = Aw1[8*SA + k0];
      af[1][2] = Aw1[k0 + 4];   af[1][3] = Aw1[8*SA + k0 + 4];
      #pragma unroll
      for(int nj = 0; nj < 8; nj++){
        uint32_t b0 = Bw1[nj*8*SA + k0];
        uint32_t b1 = Bw1[nj*8*SA + k0 + 4];
        mma_tf32(acc[0][nj][0], acc[0][nj][1], acc[0][nj][2], acc[0][nj][3],
                 af[0][0], af[0][1], af[0][2], af[0][3], b0, b1);
        mma_tf32(acc[1][nj][0], acc[1][nj][1], acc[1][nj][2], acc[1][nj][3],
                 af[1][0], af[1][1], af[1][2], af[1][3], b0, b1);
      }
    }
    if(ch + 1 < NCH) __syncthreads();
  }

  float cs[8][2];
  if(POOL){
    #pragma unroll
    for(int nj=0;nj<8;nj++){ cs[nj][0]=0.f; cs[nj][1]=0.f; }
  }

  #pragma unroll
  for(int mi = 0; mi < 2; mi++){
    #pragma unroll
    for(int nj = 0; nj < 8; nj++){
      int c = col0 + n0 + nj*8 + t4*2;
      #pragma unroll
      for(int h = 0; h < 2; h++){
        int r = row0 + m0 + mi*16 + g + h*8;
        float v0 = acc[mi][nj][h*2+0] + bias[c];
        float v1 = acc[mi][nj][h*2+1] + bias[c+1];
        if(POOL){ cs[nj][0] += v0; cs[nj][1] += v1; }
        if(RND){
          *(uint2*)(C + (size_t)r*Ndt + c) = make_uint2(f2tf32(v0), f2tf32(v1));
        } else {
          *(float2*)(C + (size_t)r*Ndt + c) = make_float2(v0, v1);
        }
      }
    }
  }

  if(POOL){
    int graph = row0 >> 9;
    #pragma unroll
    for(int nj = 0; nj < 8; nj++){
      float s0 = cs[nj][0], s1 = cs[nj][1];
      #pragma unroll
      for(int o = 4; o <= 16; o <<= 1){
        s0 += __shfl_xor_sync(0xffffffffu, s0, o);
        s1 += __shfl_xor_sync(0xffffffffu, s1, o);
      }
      if(g == 0){
        int c = col0 + n0 + nj*8 + t4*2;
        atomicAdd(&emb[graph*HIDD + c],   s0*(1.0f/PN));
        atomicAdd(&emb[graph*HIDD + c+1], s1*(1.0f/PN));
      }
    }
  }
}

// ================= attention via tf32 mma: CTA per (graph, head, half) ===========
#define KSTR 36
#define VSTR 40
#define SSTR 516
#define QSTR 36
#define KS_OFF 0
#define VS_OFF (512*KSTR)
#define S_OFF  (VS_OFF + 512*VSTR)
#define Q_OFF  (S_OFF + 32*SSTR)
#define SINV_OFF (Q_OFF + 32*QSTR)
#define ATTN_FLOATS (SINV_OFF + 32)

__global__ __launch_bounds__(256)
void attn_mma_kernel(const float* __restrict__ qkv, float* __restrict__ out){
  extern __shared__ float smf[];
  float* S    = smf + S_OFF;
  float* Sinv = smf + SINV_OFF;
  uint32_t* Ku = (uint32_t*)(smf + KS_OFF);
  uint32_t* Vu = (uint32_t*)(smf + VS_OFF);
  uint32_t* Su = (uint32_t*)S;
  uint32_t* Qu = (uint32_t*)(smf + Q_OFF);

  int g    = blockIdx.x >> 3;
  int hd   = (blockIdx.x >> 1) & 3;
  int half = blockIdx.x & 1;
  int n0 = g*PN;
  int t = threadIdx.x;
  int lane = t & 31, warp = t >> 5;
  int gq = lane >> 2, t4 = lane & 3;
  const float scale = 0.17677669529663687f;

  for(int idx = t; idx < PN*8; idx += 256){
    int r = idx >> 3, d4 = (idx & 7)*4;
    const uint32_t* row = (const uint32_t*)qkv + (size_t)(n0 + r)*384 + hd*32;
    *(uint4*)(Ku + r*KSTR + d4) = *(const uint4*)(row + 128 + d4);
    *(uint4*)(Vu + r*VSTR + d4) = *(const uint4*)(row + 256 + d4);
  }
  __syncthreads();

  for(int qi8 = 0; qi8 < 8; qi8++){
    int qt = half*8 + qi8;
    for(int idx = t; idx < 32*8; idx += 256){
      int r = idx >> 3, d4 = (idx & 7)*4;
      *(uint4*)(Qu + r*QSTR + d4) =
        *(const uint4*)((const uint32_t*)qkv + (size_t)(n0 + qt*32 + r)*384 + hd*32 + d4);
    }
    __syncthreads();

    // Phase A: S = Q K^T (unscaled)
    {
      float c[2][8][4];
      #pragma unroll
      for(int i=0;i<2;i++)
        #pragma unroll
        for(int j=0;j<8;j++)
          #pragma unroll
          for(int q=0;q<4;q++) c[i][j][q]=0.f;

      #pragma unroll 1
      for(int ks = 0; ks < 4; ks++){
        int k0 = ks*8;
        uint32_t a[2][4];
        #pragma unroll
        for(int mi=0;mi<2;mi++){
          const uint32_t* qb = Qu + (mi*16+gq)*QSTR + k0 + t4;
          a[mi][0]=qb[0]; a[mi][1]=qb[8*QSTR]; a[mi][2]=qb[4]; a[mi][3]=qb[8*QSTR+4];
        }
        #pragma unroll
        for(int nj=0;nj<8;nj++){
          const uint32_t* kb = Ku + (warp*64+nj*8+gq)*KSTR + k0 + t4;
          uint32_t b0 = kb[0], b1 = kb[4];
          mma_tf32(c[0][nj][0],c[0][nj][1],c[0][nj][2],c[0][nj][3],
                   a[0][0],a[0][1],a[0][2],a[0][3], b0,b1);
          mma_tf32(c[1][nj][0],c[1][nj][1],c[1][nj][2],c[1][nj][3],
                   a[1][0],a[1][1],a[1][2],a[1][3], b0,b1);
        }
      }
      #pragma unroll
      for(int mi=0;mi<2;mi++)
        #pragma unroll
        for(int nj=0;nj<8;nj++){
          float* sp = S + (mi*16+gq)*SSTR + warp*64 + nj*8 + t4*2;
          *(float2*)(sp)          = make_float2(c[mi][nj][0], c[mi][nj][1]);
          *(float2*)(sp + 8*SSTR) = make_float2(c[mi][nj][2], c[mi][nj][3]);
        }
    }
    __syncthreads();

    // Phase B: exp(s*scale) + sum; normalization deferred
    for(int rr = 0; rr < 4; rr++){
      int r = warp*4 + rr;
      float sum = 0.f;
      float* Srow = S + r*SSTR;
      #pragma unroll
      for(int jj = 0; jj < 4; jj++){
        int j4 = (jj*32 + lane)*4;
        float4 v = *(float4*)(Srow + j4);
        v.x = __expf(v.x*scale); v.y = __expf(v.y*scale);
        v.z = __expf(v.z*scale); v.w = __expf(v.w*scale);
        sum += v.x + v.y + v.z + v.w;
        *(uint4*)((uint32_t*)Srow + j4) = q4(v);
      }
      #pragma unroll
      for(int o=16;o;o>>=1) sum += __shfl_xor_sync(0xffffffffu, sum, o);
      if(lane == 0) Sinv[r] = 1.f/sum;
    }
    __syncthreads();

    // Phase C: O = (E V) * Sinv; output rounded (feeds final GEMM)
    {
      int mi = warp & 1, ni = warp >> 1;
      float c0=0.f,c1=0.f,c2=0.f,c3=0.f;
      const uint32_t* pbase = Su + (mi*16+gq)*SSTR + t4;
      const uint32_t* vbase = Vu + t4*VSTR + ni*8 + gq;
      #pragma unroll 4
      for(int ks = 0; ks < 64; ks++){
        int k0 = ks*8;
        uint32_t a0 = pbase[k0], a1 = pbase[8*SSTR + k0];
        uint32_t a2 = pbase[k0+4], a3 = pbase[8*SSTR + k0+4];
        uint32_t b0 = vbase[k0*VSTR], b1 = vbase[(k0+4)*VSTR];
        mma_tf32(c0,c1,c2,c3, a0,a1,a2,a3, b0,b1);
      }
      int r0 = mi*16 + gq;
      float inv0 = Sinv[r0], inv1 = Sinv[r0+8];
      float* ob = out + (size_t)(n0 + qt*32)*HIDD + hd*32 + ni*8 + t4*2;
      *(uint2*)(ob + (size_t)r0*HIDD)     = make_uint2(f2tf32(c0*inv0), f2tf32(c1*inv0));
      *(uint2*)(ob + (size_t)(r0+8)*HIDD) = make_uint2(f2tf32(c2*inv1), f2tf32(c3*inv1));
    }
    __syncthreads();
  }
}

// ================= launch =================
extern "C" void kernel_launch(void* const* d_in, const int* in_sizes, int n_in,
                              void* d_out, int out_size) {
  const float* x   = (const float*)d_in[0];
  const float* W0  = (const float*)d_in[1];
  const float* b0  = (const float*)d_in[2];
  const float* Wh  = (const float*)d_in[3];
  const float* bh  = (const float*)d_in[4];
  const float* bng = (const float*)d_in[5];
  const float* bnb = (const float*)d_in[6];
  const float* bnm = (const float*)d_in[7];
  const float* bnv = (const float*)d_in[8];
  const float* aiw = (const float*)d_in[9];
  const float* aib = (const float*)d_in[10];
  const float* aow = (const float*)d_in[11];
  const float* aob = (const float*)d_in[12];
  const int*  eidx = (const int*)d_in[13];

  float* out_final = (float*)d_out;
  float* out_emb   = out_final + (size_t)NN*HIDD;

  const int* src = eidx;
  const int* dst = eidx + NE;

  float *p_h, *p_h2, *p_qkv, *p_attno;
  int* p_count;
  uint32_t* p_wr;
  cudaGetSymbolAddress((void**)&p_h,     g_h);
  cudaGetSymbolAddress((void**)&p_h2,    g_h2);
  cudaGetSymbolAddress((void**)&p_qkv,   g_qkv);
  cudaGetSymbolAddress((void**)&p_attno, g_attno);
  cudaGetSymbolAddress((void**)&p_count, g_count);
  cudaGetSymbolAddress((void**)&p_wr,    g_wr);

  const int AG128_SMEM = (128*132 + 2*32*132)*4;   // 101376
  const int AG64_SMEM  = (128*68  + 2*32*132)*4;   // 68608
  const int GEMM_SMEM  = 2*9216*4;                 // 73728
  const int ATTN_SMEM  = ATTN_FLOATS*4;            // 226432
  cudaFuncSetAttribute(agggemm_kernel<64>,  cudaFuncAttributeMaxDynamicSharedMemorySize, AG64_SMEM);
  cudaFuncSetAttribute(agggemm_kernel<128>, cudaFuncAttributeMaxDynamicSharedMemorySize, AG128_SMEM);
  cudaFuncSetAttribute(gemm_mma_kernel<0,1>, cudaFuncAttributeMaxDynamicSharedMemorySize, GEMM_SMEM);
  cudaFuncSetAttribute(gemm_mma_kernel<1,0>, cudaFuncAttributeMaxDynamicSharedMemorySize, GEMM_SMEM);
  cudaFuncSetAttribute(attn_mma_kernel,      cudaFuncAttributeMaxDynamicSharedMemorySize, ATTN_SMEM);

  // weight pre-round (independent of CSR chain)
  roundw_kernel<<<120, 256>>>(W0, Wh, aiw, aow);

  // CSR build
  cudaMemsetAsync(p_count, 0, NN*sizeof(int));
  count_kernel<<<NE/256, 256>>>(dst);
  scan1_kernel<<<256, 256>>>();
  scan23_kernel<<<256, 256>>>();
  fill_kernel<<<NE/256, 256>>>(src, dst);

  // fused GCN layers (ping-pong: x->h, h->h2, h2->h, h->h2)
  agggemm_kernel<64><<<512, 256, AG64_SMEM>>>(
      x, p_wr, b0, bng, bnb, bnm, bnv, p_h);
  agggemm_kernel<128><<<512, 256, AG128_SMEM>>>(
      p_h, p_wr + 8192, bh, bng + HIDD, bnb + HIDD, bnm + HIDD, bnv + HIDD, p_h2);
  agggemm_kernel<128><<<512, 256, AG128_SMEM>>>(
      p_h2, p_wr + 8192 + 16384, bh + HIDD,
      bng + 2*HIDD, bnb + 2*HIDD, bnm + 2*HIDD, bnv + 2*HIDD, p_h);
  agggemm_kernel<128><<<512, 256, AG128_SMEM>>>(
      p_h, p_wr + 8192 + 2*16384, bh + 2*HIDD,
      bng + 3*HIDD, bnb + 3*HIDD, bnm + 3*HIDD, bnv + 3*HIDD, p_h2);

  // qkv projection (output rounded for attention)
  gemm_mma_kernel<0,1><<<dim3(512,3), 256, GEMM_SMEM>>>(
      p_h2, p_wr + 57344, aib, p_qkv, 384, nullptr);

  // attention
  attn_mma_kernel<<<NG*4*2, 256, ATTN_SMEM>>>(p_qkv, p_attno);

  // output projection + fused mean pool (unrounded terminal output)
  cudaMemsetAsync(out_emb, 0, NG*HIDD*sizeof(float));
  gemm_mma_kernel<1,0><<<dim3(512,1), 256, GEMM_SMEM>>>(
      p_attno, p_wr + 106496, aob, out_final, 128, out_emb);
}

// round 14
// speedup vs baseline: 1.2147x; 1.2147x over previous
#include <cuda_runtime.h>
#include <cstdint>

#define NN 65536
#define NE (NN*16)
#define NG 128
#define PN 512
#define HIDD 128
#define INDIM 64
#define BN_EPS 1e-5f

__device__ __forceinline__ uint32_t f2tf32(float f){
  uint32_t u; asm("cvt.rna.tf32.f32 %0, %1;" : "=r"(u) : "f"(f)); return u;
}
__device__ __forceinline__ void mma_tf32(float& c0, float& c1, float& c2, float& c3,
                                         uint32_t a0, uint32_t a1, uint32_t a2, uint32_t a3,
                                         uint32_t b0, uint32_t b1){
  asm volatile("mma.sync.aligned.m16n8k8.row.col.f32.tf32.tf32.f32 "
               "{%0,%1,%2,%3}, {%4,%5,%6,%7}, {%8,%9}, {%0,%1,%2,%3};"
               : "+f"(c0), "+f"(c1), "+f"(c2), "+f"(c3)
               : "r"(a0), "r"(a1), "r"(a2), "r"(a3), "r"(b0), "r"(b1));
}
__device__ __forceinline__ uint4 q4(float4 v){
  return make_uint4(f2tf32(v.x), f2tf32(v.y), f2tf32(v.z), f2tf32(v.w));
}
__device__ __forceinline__ void cp16(uint32_t* dst, const uint32_t* src){
  uint32_t d = (uint32_t)__cvta_generic_to_shared(dst);
  asm volatile("cp.async.cg.shared.global [%0], [%1], 16;" :: "r"(d), "l"(src));
}
#define CP_COMMIT() asm volatile("cp.async.commit_group;" ::: "memory")

// ================= scratch =================
__device__ int    g_count[NN];
__device__ int    g_rowptr[NN+1];
__device__ int    g_cursor[NN];
__device__ int    g_part[256];
__device__ float2 g_edge[NE];     // (src bits, weight)
__device__ float  g_dis[NN];
__device__ float  g_selfn[NN];
__device__ float  g_h[(size_t)NN*HIDD];
__device__ float  g_agg[(size_t)NN*HIDD];
__device__ float  g_qkv[(size_t)NN*3*HIDD];
__device__ float  g_attno[(size_t)NN*HIDD];
__device__ uint32_t g_wr[122880];   // pre-rounded weights: W0|Wh|aiw|aow

// ================= weight pre-round (tf32) =================
__global__ void roundw_kernel(const float* __restrict__ W0, const float* __restrict__ Wh,
                              const float* __restrict__ aiw, const float* __restrict__ aow){
  int i = (blockIdx.x*256 + threadIdx.x)*4;
  float4 v;
  if(i < 8192)        v = *(const float4*)(W0 + i);
  else if(i < 57344)  v = *(const float4*)(Wh + (i - 8192));
  else if(i < 106496) v = *(const float4*)(aiw + (i - 57344));
  else                v = *(const float4*)(aow + (i - 106496));
  *(uint4*)(g_wr + i) = q4(v);
}

// ================= CSR build =================
__global__ void count_kernel(const int* __restrict__ dst){
  int e = blockIdx.x*blockDim.x + threadIdx.x;
  if(e < NE) atomicAdd(&g_count[dst[e]], 1);
}
__global__ void scan1_kernel(){
  __shared__ int wsum[8];
  int b = blockIdx.x, t = threadIdx.x;
  int i = b*256 + t;
  int c = g_count[i];
  float dis = rsqrtf((float)(c + 1));
  g_dis[i] = dis;
  g_selfn[i] = dis*dis;
  int lane = t & 31, w = t >> 5;
  int v = c;
  #pragma unroll
  for(int o=1;o<32;o<<=1){ int u=__shfl_up_sync(0xffffffffu,v,o); if(lane>=o) v+=u; }
  if(lane==31) wsum[w]=v;
  __syncthreads();
  if(w==0){
    int s = (lane<8)? wsum[lane] : 0;
    #pragma unroll
    for(int o=1;o<8;o<<=1){ int u=__shfl_up_sync(0xffffffffu,s,o); if(lane>=o) s+=u; }
    if(lane<8) wsum[lane]=s;
  }
  __syncthreads();
  int excl = v - c + (w ? wsum[w-1] : 0);
  g_rowptr[i] = excl;
  if(t==255) g_part[b] = excl + c;
}
// merged scan2+scan3: each block redundantly reduces partials below its id
__global__ void scan23_kernel(){
  __shared__ int red[8];
  int b = blockIdx.x, t = threadIdx.x;
  int lane = t & 31, w = t >> 5;
  int v = (t < b) ? g_part[t] : 0;
  #pragma unroll
  for(int o=16;o;o>>=1) v += __shfl_xor_sync(0xffffffffu, v, o);
  if(lane == 0) red[w] = v;
  __syncthreads();
  if(w == 0){
    int s = (lane < 8) ? red[lane] : 0;
    #pragma unroll
    for(int o=4;o;o>>=1) s += __shfl_xor_sync(0xffffffffu, s, o);
    if(lane == 0) red[0] = s;
  }
  __syncthreads();
  int poff = red[0];
  int i = b*256 + t;
  int r = g_rowptr[i] + poff;
  g_rowptr[i] = r;
  g_cursor[i] = r;
  if(i == 0) g_rowptr[NN] = NE;
}
__global__ void fill_kernel(const int* __restrict__ src, const int* __restrict__ dst){
  int e = blockIdx.x*blockDim.x + threadIdx.x;
  if(e >= NE) return;
  int s = src[e], d = dst[e];
  int pos = atomicAdd(&g_cursor[d], 1);
  g_edge[pos] = make_float2(__int_as_float(s), g_dis[s]*g_dis[d]);
}

// ======== aggregation (warp/node; edge prefetch + shfl bcast; tf32-rounded output) ========
__global__ void agg64_kernel(const float* __restrict__ hin, float* __restrict__ out){
  int gw = (blockIdx.x*blockDim.x + threadIdx.x) >> 5;
  int lane = threadIdx.x & 31;
  if(gw >= NN) return;
  float2 a = *((const float2*)(hin + (size_t)gw*INDIM) + lane);
  float sn = g_selfn[gw];
  a.x *= sn; a.y *= sn;
  int beg = g_rowptr[gw], end = g_rowptr[gw+1];
  for(int b = beg; b < end; b += 32){
    int m = min(32, end - b);
    float2 myed = make_float2(0.f, 0.f);
    if(lane < m) myed = g_edge[b + lane];
    #pragma unroll 4
    for(int i = 0; i < m; i++){
      int   s = __shfl_sync(0xffffffffu, __float_as_int(myed.x), i);
      float w = __shfl_sync(0xffffffffu, myed.y, i);
      float2 v = *((const float2*)(hin + (size_t)s*INDIM) + lane);
      a.x += w*v.x; a.y += w*v.y;
    }
  }
  *((uint2*)(out + (size_t)gw*INDIM) + lane) = make_uint2(f2tf32(a.x), f2tf32(a.y));
}
__global__ void agg128_kernel(const float* __restrict__ hin, float* __restrict__ out){
  int gw = (blockIdx.x*blockDim.x + threadIdx.x) >> 5;
  int lane = threadIdx.x & 31;
  if(gw >= NN) return;
  float4 a = *((const float4*)(hin + (size_t)gw*HIDD) + lane);
  float sn = g_selfn[gw];
  a.x *= sn; a.y *= sn; a.z *= sn; a.w *= sn;
  int beg = g_rowptr[gw], end = g_rowptr[gw+1];
  for(int b = beg; b < end; b += 32){
    int m = min(32, end - b);
    float2 myed = make_float2(0.f, 0.f);
    if(lane < m) myed = g_edge[b + lane];
    #pragma unroll 4
    for(int i = 0; i < m; i++){
      int   s = __shfl_sync(0xffffffffu, __float_as_int(myed.x), i);
      float w = __shfl_sync(0xffffffffu, myed.y, i);
      float4 v = *((const float4*)(hin + (size_t)s*HIDD) + lane);
      a.x += w*v.x; a.y += w*v.y; a.z += w*v.z; a.w += w*v.w;
    }
  }
  *((uint4*)(out + (size_t)gw*HIDD) + lane) = q4(a);
}

// ========== tf32 mma.sync GEMM: cp.async double-buffered, CK=32, 2 CTAs/SM ==========
// A, B point to pre-rounded tf32 bits. RND=1: round outputs. POOL=1: fused mean pool.
template<int BT, int EPI, int KK, int POOL, int RND>
__global__ __launch_bounds__(256, 2)
void gemm_mma_kernel(const float* __restrict__ A, const uint32_t* __restrict__ B,
                     const float* __restrict__ bias,
                     const float* __restrict__ bng, const float* __restrict__ bnb,
                     const float* __restrict__ bnm, const float* __restrict__ bnv,
                     float* __restrict__ C, int Ndt, float* __restrict__ emb)
{
  constexpr int CK  = 32;
  constexpr int NCH = KK / CK;
  constexpr int SA  = 36;          // A (and BT1 B) row stride in u32
  constexpr int SBN = 132;         // BT0 B row stride
  constexpr int BUFA = 128*SA;     // 4608 u32
  constexpr int BUF  = 2*BUFA;     // 9216 u32 per stage buffer (A + B)
  extern __shared__ uint32_t sm[];
  const int tid = threadIdx.x;
  const int lane = tid & 31, wid = tid >> 5;
  const int row0 = blockIdx.x * 128;
  const int col0 = blockIdx.y * 128;
  const uint32_t* Ag = (const uint32_t*)A;

  const int m0 = (wid >> 1) * 32;
  const int n0 = (wid & 1) * 64;
  const int g  = lane >> 2;
  const int t4 = lane & 3;

  float acc[2][8][4];
  #pragma unroll
  for(int i=0;i<2;i++)
    #pragma unroll
    for(int j=0;j<8;j++)
      #pragma unroll
      for(int q=0;q<4;q++) acc[i][j][q]=0.f;

  auto stage = [&](int ch){
    const int kbase = ch*CK;
    uint32_t* As = sm + (ch & 1)*BUF;
    uint32_t* Bs = As + BUFA;
    #pragma unroll
    for(int i = 0; i < 4; i++){
      int idx = tid + i*256;
      int r = idx >> 3, q = idx & 7;
      cp16(As + r*SA + q*4, Ag + (size_t)(row0 + r)*KK + kbase + q*4);
    }
    if(BT){
      #pragma unroll
      for(int i = 0; i < 4; i++){
        int idx = tid + i*256;
        int r = idx >> 3, q = idx & 7;
        cp16(Bs + r*SA + q*4, B + (size_t)(col0 + r)*KK + kbase + q*4);
      }
    } else {
      #pragma unroll
      for(int i = 0; i < 4; i++){
        int idx = tid + i*256;
        int k = idx >> 5, n4 = idx & 31;
        cp16(Bs + k*SBN + n4*4, B + (size_t)(kbase + k)*Ndt + col0 + n4*4);
      }
    }
    CP_COMMIT();
  };

  stage(0);

  #pragma unroll 1
  for(int ch = 0; ch < NCH; ch++){
    if(ch + 1 < NCH) stage(ch + 1);
    if(ch + 1 < NCH) asm volatile("cp.async.wait_group 1;" ::: "memory");
    else             asm volatile("cp.async.wait_group 0;" ::: "memory");
    __syncthreads();

    uint32_t* As = sm + (ch & 1)*BUF;
    uint32_t* Bs = As + BUFA;
    const uint32_t* Aw0 = As + (m0 + g)*SA + t4;
    const uint32_t* Aw1 = As + (m0 + 16 + g)*SA + t4;
    const uint32_t* Bw1 = Bs + (n0 + g)*SA + t4;
    const uint32_t* Bw0 = Bs + t4*SBN + n0 + g;

    #pragma unroll 1
    for(int ks = 0; ks < CK/8; ks++){
      const int k0 = ks*8;
      uint32_t af[2][4];
      af[0][0] = Aw0[k0];       af[0][1] = Aw0[8*SA + k0];
      af[0][2] = Aw0[k0 + 4];   af[0][3] = Aw0[8*SA + k0 + 4];
      af[1][0] = Aw1[k0];       af[1][1] = Aw1[8*SA + k0];
      af[1][2] = Aw1[k0 + 4];   af[1][3] = Aw1[8*SA + k0 + 4];
      #pragma unroll
      for(int nj = 0; nj < 8; nj++){
        uint32_t b0, b1;
        if(BT){
          b0 = Bw1[nj*8*SA + k0];
          b1 = Bw1[nj*8*SA + k0 + 4];
        } else {
          b0 = Bw0[k0*SBN + nj*8];
          b1 = Bw0[(k0+4)*SBN + nj*8];
        }
        mma_tf32(acc[0][nj][0], acc[0][nj][1], acc[0][nj][2], acc[0][nj][3],
                 af[0][0], af[0][1], af[0][2], af[0][3], b0, b1);
        mma_tf32(acc[1][nj][0], acc[1][nj][1], acc[1][nj][2], acc[1][nj][3],
                 af[1][0], af[1][1], af[1][2], af[1][3], b0, b1);
      }
    }
    if(ch + 1 < NCH) __syncthreads();   // protect buffer (ch&1) before chunk ch+2 staging
  }

  float cs[8][2];
  if(POOL){
    #pragma unroll
    for(int nj=0;nj<8;nj++){ cs[nj][0]=0.f; cs[nj][1]=0.f; }
  }

  #pragma unroll
  for(int mi = 0; mi < 2; mi++){
    #pragma unroll
    for(int nj = 0; nj < 8; nj++){
      int c = col0 + n0 + nj*8 + t4*2;
      float s0, s1;
      if(EPI){
        s0 = bng[c  ]*rsqrtf(bnv[c  ] + BN_EPS);
        s1 = bng[c+1]*rsqrtf(bnv[c+1] + BN_EPS);
      }
      #pragma unroll
      for(int h = 0; h < 2; h++){
        int r = row0 + m0 + mi*16 + g + h*8;
        float v0 = acc[mi][nj][h*2+0] + bias[c];
        float v1 = acc[mi][nj][h*2+1] + bias[c+1];
        if(EPI){
          v0 = fmaxf((v0 - bnm[c  ])*s0 + bnb[c  ], 0.f);
          v1 = fmaxf((v1 - bnm[c+1])*s1 + bnb[c+1], 0.f);
        }
        if(POOL){ cs[nj][0] += v0; cs[nj][1] += v1; }
        if(RND){
          *(uint2*)(C + (size_t)r*Ndt + c) = make_uint2(f2tf32(v0), f2tf32(v1));
        } else {
          *(float2*)(C + (size_t)r*Ndt + c) = make_float2(v0, v1);
        }
      }
    }
  }

  if(POOL){
    int graph = row0 >> 9;
    #pragma unroll
    for(int nj = 0; nj < 8; nj++){
      float s0 = cs[nj][0], s1 = cs[nj][1];
      #pragma unroll
      for(int o = 4; o <= 16; o <<= 1){
        s0 += __shfl_xor_sync(0xffffffffu, s0, o);
        s1 += __shfl_xor_sync(0xffffffffu, s1, o);
      }
      if(g == 0){
        int c = col0 + n0 + nj*8 + t4*2;
        atomicAdd(&emb[graph*HIDD + c],   s0*(1.0f/PN));
        atomicAdd(&emb[graph*HIDD + c+1], s1*(1.0f/PN));
      }
    }
  }
}

// ================= attention via tf32 mma: CTA per (graph, head, half) ===========
// qkv is pre-rounded tf32 bits -> staging is pure copy; 1/sqrt(32) folded into exp.
#define KSTR 36
#define VSTR 40
#define SSTR 516
#define QSTR 36
#define KS_OFF 0
#define VS_OFF (512*KSTR)
#define S_OFF  (VS_OFF + 512*VSTR)
#define Q_OFF  (S_OFF + 32*SSTR)
#define SINV_OFF (Q_OFF + 32*QSTR)
#define ATTN_FLOATS (SINV_OFF + 32)

__global__ __launch_bounds__(256)
void attn_mma_kernel(const float* __restrict__ qkv, float* __restrict__ out){
  extern __shared__ float smf[];
  float* S    = smf + S_OFF;
  float* Sinv = smf + SINV_OFF;
  uint32_t* Ku = (uint32_t*)(smf + KS_OFF);
  uint32_t* Vu = (uint32_t*)(smf + VS_OFF);
  uint32_t* Su = (uint32_t*)S;
  uint32_t* Qu = (uint32_t*)(smf + Q_OFF);

  int g    = blockIdx.x >> 3;
  int hd   = (blockIdx.x >> 1) & 3;
  int half = blockIdx.x & 1;
  int n0 = g*PN;
  int t = threadIdx.x;
  int lane = t & 31, warp = t >> 5;
  int gq = lane >> 2, t4 = lane & 3;
  const float scale = 0.17677669529663687f;   // 1/sqrt(32), folded into exp

  for(int idx = t; idx < PN*8; idx += 256){
    int r = idx >> 3, d4 = (idx & 7)*4;
    const uint32_t* row = (const uint32_t*)qkv + (size_t)(n0 + r)*384 + hd*32;
    *(uint4*)(Ku + r*KSTR + d4) = *(const uint4*)(row + 128 + d4);
    *(uint4*)(Vu + r*VSTR + d4) = *(const uint4*)(row + 256 + d4);
  }
  __syncthreads();

  for(int qi8 = 0; qi8 < 8; qi8++){
    int qt = half*8 + qi8;
    for(int idx = t; idx < 32*8; idx += 256){
      int r = idx >> 3, d4 = (idx & 7)*4;
      *(uint4*)(Qu + r*QSTR + d4) =
        *(const uint4*)((const uint32_t*)qkv + (size_t)(n0 + qt*32 + r)*384 + hd*32 + d4);
    }
    __syncthreads();

    // Phase A: S = Q K^T (unscaled)
    {
      float c[2][8][4];
      #pragma unroll
      for(int i=0;i<2;i++)
        #pragma unroll
        for(int j=0;j<8;j++)
          #pragma unroll
          for(int q=0;q<4;q++) c[i][j][q]=0.f;

      #pragma unroll 1
      for(int ks = 0; ks < 4; ks++){
        int k0 = ks*8;
        uint32_t a[2][4];
        #pragma unroll
        for(int mi=0;mi<2;mi++){
          const uint32_t* qb = Qu + (mi*16+gq)*QSTR + k0 + t4;
          a[mi][0]=qb[0]; a[mi][1]=qb[8*QSTR]; a[mi][2]=qb[4]; a[mi][3]=qb[8*QSTR+4];
        }
        #pragma unroll
        for(int nj=0;nj<8;nj++){
          const uint32_t* kb = Ku + (warp*64+nj*8+gq)*KSTR + k0 + t4;
          uint32_t b0 = kb[0], b1 = kb[4];
          mma_tf32(c[0][nj][0],c[0][nj][1],c[0][nj][2],c[0][nj][3],
                   a[0][0],a[0][1],a[0][2],a[0][3], b0,b1);
          mma_tf32(c[1][nj][0],c[1][nj][1],c[1][nj][2],c[1][nj][3],
                   a[1][0],a[1][1],a[1][2],a[1][3], b0,b1);
        }
      }
      #pragma unroll
      for(int mi=0;mi<2;mi++)
        #pragma unroll
        for(int nj=0;nj<8;nj++){
          float* sp = S + (mi*16+gq)*SSTR + warp*64 + nj*8 + t4*2;
          *(float2*)(sp)          = make_float2(c[mi][nj][0], c[mi][nj][1]);
          *(float2*)(sp + 8*SSTR) = make_float2(c[mi][nj][2], c[mi][nj][3]);
        }
    }
    __syncthreads();

    // Phase B: exp(s*scale) + sum (float4); normalization deferred
    for(int rr = 0; rr < 4; rr++){
      int r = warp*4 + rr;
      float sum = 0.f;
      float* Srow = S + r*SSTR;
      #pragma unroll
      for(int jj = 0; jj < 4; jj++){
        int j4 = (jj*32 + lane)*4;
        float4 v = *(float4*)(Srow + j4);
        v.x = __expf(v.x*scale); v.y = __expf(v.y*scale);
        v.z = __expf(v.z*scale); v.w = __expf(v.w*scale);
        sum += v.x + v.y + v.z + v.w;
        *(uint4*)((uint32_t*)Srow + j4) = q4(v);
      }
      #pragma unroll
      for(int o=16;o;o>>=1) sum += __shfl_xor_sync(0xffffffffu, sum, o);
      if(lane == 0) Sinv[r] = 1.f/sum;
    }
    __syncthreads();

    // Phase C: O = (E V) * Sinv; output rounded (feeds final GEMM)
    {
      int mi = warp & 1, ni = warp >> 1;
      float c0=0.f,c1=0.f,c2=0.f,c3=0.f;
      const uint32_t* pbase = Su + (mi*16+gq)*SSTR + t4;
      const uint32_t* vbase = Vu + t4*VSTR + ni*8 + gq;
      #pragma unroll 4
      for(int ks = 0; ks < 64; ks++){
        int k0 = ks*8;
        uint32_t a0 = pbase[k0], a1 = pbase[8*SSTR + k0];
        uint32_t a2 = pbase[k0+4], a3 = pbase[8*SSTR + k0+4];
        uint32_t b0 = vbase[k0*VSTR], b1 = vbase[(k0+4)*VSTR];
        mma_tf32(c0,c1,c2,c3, a0,a1,a2,a3, b0,b1);
      }
      int r0 = mi*16 + gq;
      float inv0 = Sinv[r0], inv1 = Sinv[r0+8];
      float* ob = out + (size_t)(n0 + qt*32)*HIDD + hd*32 + ni*8 + t4*2;
      *(uint2*)(ob + (size_t)r0*HIDD)     = make_uint2(f2tf32(c0*inv0), f2tf32(c1*inv0));
      *(uint2*)(ob + (size_t)(r0+8)*HIDD) = make_uint2(f2tf32(c2*inv1), f2tf32(c3*inv1));
    }
    __syncthreads();
  }
}

// ================= launch =================
extern "C" void kernel_launch(void* const* d_in, const int* in_sizes, int n_in,
                              void* d_out, int out_size) {
  const float* x   = (const float*)d_in[0];
  const float* W0  = (const float*)d_in[1];
  const float* b0  = (const float*)d_in[2];
  const float* Wh  = (const float*)d_in[3];
  const float* bh  = (const float*)d_in[4];
  const float* bng = (const float*)d_in[5];
  const float* bnb = (const float*)d_in[6];
  const float* bnm = (const float*)d_in[7];
  const float* bnv = (const float*)d_in[8];
  const float* aiw = (const float*)d_in[9];
  const float* aib = (const float*)d_in[10];
  const float* aow = (const float*)d_in[11];
  const float* aob = (const float*)d_in[12];
  const int*  eidx = (const int*)d_in[13];

  float* out_final = (float*)d_out;
  float* out_emb   = out_final + (size_t)NN*HIDD;

  const int* src = eidx;
  const int* dst = eidx + NE;

  float *p_h, *p_agg, *p_qkv, *p_attno;
  int* p_count;
  uint32_t* p_wr;
  cudaGetSymbolAddress((void**)&p_h,     g_h);
  cudaGetSymbolAddress((void**)&p_agg,   g_agg);
  cudaGetSymbolAddress((void**)&p_qkv,   g_qkv);
  cudaGetSymbolAddress((void**)&p_attno, g_attno);
  cudaGetSymbolAddress((void**)&p_count, g_count);
  cudaGetSymbolAddress((void**)&p_wr,    g_wr);

  const int GEMM_SMEM = 2*9216*4;         // 73728: 2 stage buffers
  const int ATTN_SMEM = ATTN_FLOATS*4;    // 226432
  cudaFuncSetAttribute(gemm_mma_kernel<0,1,64,0,1>,  cudaFuncAttributeMaxDynamicSharedMemorySize, GEMM_SMEM);
  cudaFuncSetAttribute(gemm_mma_kernel<0,1,128,0,1>, cudaFuncAttributeMaxDynamicSharedMemorySize, GEMM_SMEM);
  cudaFuncSetAttribute(gemm_mma_kernel<1,0,128,0,1>, cudaFuncAttributeMaxDynamicSharedMemorySize, GEMM_SMEM);
  cudaFuncSetAttribute(gemm_mma_kernel<1,0,128,1,0>, cudaFuncAttributeMaxDynamicSharedMemorySize, GEMM_SMEM);
  cudaFuncSetAttribute(attn_mma_kernel,              cudaFuncAttributeMaxDynamicSharedMemorySize, ATTN_SMEM);

  // weight pre-round (independent of CSR chain)
  roundw_kernel<<<120, 256>>>(W0, Wh, aiw, aow);

  // CSR build
  cudaMemsetAsync(p_count, 0, NN*sizeof(int));
  count_kernel<<<NE/256, 256>>>(dst);
  scan1_kernel<<<256, 256>>>();
  scan23_kernel<<<256, 256>>>();
  fill_kernel<<<NE/256, 256>>>(src, dst);

  // layer 0
  agg64_kernel<<<NN*32/256, 256>>>(x, p_agg);
  gemm_mma_kernel<0,1,64,0,1><<<dim3(512,1), 256, GEMM_SMEM>>>(
      p_agg, p_wr, b0, bng, bnb, bnm, bnv, p_h, 128, nullptr);

  // layers 1..3
  for(int l = 0; l < 3; l++){
    agg128_kernel<<<NN*32/256, 256>>>(p_h, p_agg);
    gemm_mma_kernel<0,1,128,0,1><<<dim3(512,1), 256, GEMM_SMEM>>>(
        p_agg, p_wr + 8192 + l*16384, bh + l*HIDD,
        bng + (l+1)*HIDD, bnb + (l+1)*HIDD, bnm + (l+1)*HIDD, bnv + (l+1)*HIDD,
        p_h, 128, nullptr);
  }

  // qkv projection (output rounded for attention)
  gemm_mma_kernel<1,0,128,0,1><<<dim3(512,3), 256, GEMM_SMEM>>>(
      p_h, p_wr + 57344, aib, nullptr, nullptr, nullptr, nullptr, p_qkv, 384, nullptr);

  // attention
  attn_mma_kernel<<<NG*4*2, 256, ATTN_SMEM>>>(p_qkv, p_attno);

  // output projection + fused mean pool (unrounded terminal output)
  cudaMemsetAsync(out_emb, 0, NG*HIDD*sizeof(float));
  gemm_mma_kernel<1,0,128,1,0><<<dim3(512,1), 256, GEMM_SMEM>>>(
      p_attno, p_wr + 106496, aob, nullptr, nullptr, nullptr, nullptr, out_final, 128, out_emb);
}

// round 16
// speedup vs baseline: 1.2839x; 1.0569x over previous
#include <cuda_runtime.h>
#include <cstdint>

#define NN 65536
#define NE (NN*16)
#define NG 128
#define PN 512
#define HIDD 128
#define INDIM 64
#define BN_EPS 1e-5f

__device__ __forceinline__ uint32_t f2tf32(float f){
  uint32_t u; asm("cvt.rna.tf32.f32 %0, %1;" : "=r"(u) : "f"(f)); return u;
}
__device__ __forceinline__ void mma_tf32(float& c0, float& c1, float& c2, float& c3,
                                         uint32_t a0, uint32_t a1, uint32_t a2, uint32_t a3,
                                         uint32_t b0, uint32_t b1){
  asm volatile("mma.sync.aligned.m16n8k8.row.col.f32.tf32.tf32.f32 "
               "{%0,%1,%2,%3}, {%4,%5,%6,%7}, {%8,%9}, {%0,%1,%2,%3};"
               : "+f"(c0), "+f"(c1), "+f"(c2), "+f"(c3)
               : "r"(a0), "r"(a1), "r"(a2), "r"(a3), "r"(b0), "r"(b1));
}
__device__ __forceinline__ uint4 q4(float4 v){
  return make_uint4(f2tf32(v.x), f2tf32(v.y), f2tf32(v.z), f2tf32(v.w));
}
__device__ __forceinline__ void cp16(uint32_t* dst, const uint32_t* src){
  uint32_t d = (uint32_t)__cvta_generic_to_shared(dst);
  asm volatile("cp.async.cg.shared.global [%0], [%1], 16;" :: "r"(d), "l"(src));
}
#define CP_COMMIT() asm volatile("cp.async.commit_group;" ::: "memory")

// ================= scratch =================
__device__ int    g_count[NN];
__device__ int    g_rowptr[NN+1];
__device__ int    g_cursor[NN];
__device__ int    g_part[256];
__device__ float2 g_edge[NE];     // (src bits, weight)
__device__ float  g_dis[NN];
__device__ float  g_selfn[NN];
__device__ float  g_h[(size_t)NN*HIDD];
__device__ float  g_agg[(size_t)NN*HIDD];
__device__ float  g_qkv[(size_t)NN*3*HIDD];
__device__ float  g_attno[(size_t)NN*HIDD];
__device__ uint32_t g_wr[122880];   // pre-rounded weights: W0|Wh|aiw|aow

// ============ weight pre-round (tf32) + count zeroing (blocks >= 120) ============
__global__ void roundw_kernel(const float* __restrict__ W0, const float* __restrict__ Wh,
                              const float* __restrict__ aiw, const float* __restrict__ aow){
  int b = blockIdx.x;
  if(b >= 120){
    g_count[(b - 120)*256 + threadIdx.x] = 0;
    return;
  }
  int i = (b*256 + threadIdx.x)*4;
  float4 v;
  if(i < 8192)        v = *(const float4*)(W0 + i);
  else if(i < 57344)  v = *(const float4*)(Wh + (i - 8192));
  else if(i < 106496) v = *(const float4*)(aiw + (i - 57344));
  else                v = *(const float4*)(aow + (i - 106496));
  *(uint4*)(g_wr + i) = q4(v);
}

// ================= CSR build =================
__global__ void count_kernel(const int* __restrict__ dst){
  int e = blockIdx.x*blockDim.x + threadIdx.x;
  if(e < NE) atomicAdd(&g_count[dst[e]], 1);
}
__global__ void scan1_kernel(){
  __shared__ int wsum[8];
  int b = blockIdx.x, t = threadIdx.x;
  int i = b*256 + t;
  int c = g_count[i];
  float dis = rsqrtf((float)(c + 1));
  g_dis[i] = dis;
  g_selfn[i] = dis*dis;
  int lane = t & 31, w = t >> 5;
  int v = c;
  #pragma unroll
  for(int o=1;o<32;o<<=1){ int u=__shfl_up_sync(0xffffffffu,v,o); if(lane>=o) v+=u; }
  if(lane==31) wsum[w]=v;
  __syncthreads();
  if(w==0){
    int s = (lane<8)? wsum[lane] : 0;
    #pragma unroll
    for(int o=1;o<8;o<<=1){ int u=__shfl_up_sync(0xffffffffu,s,o); if(lane>=o) s+=u; }
    if(lane<8) wsum[lane]=s;
  }
  __syncthreads();
  int excl = v - c + (w ? wsum[w-1] : 0);
  g_rowptr[i] = excl;
  if(t==255) g_part[b] = excl + c;
}
// merged scan2+scan3
__global__ void scan23_kernel(){
  __shared__ int red[8];
  int b = blockIdx.x, t = threadIdx.x;
  int lane = t & 31, w = t >> 5;
  int v = (t < b) ? g_part[t] : 0;
  #pragma unroll
  for(int o=16;o;o>>=1) v += __shfl_xor_sync(0xffffffffu, v, o);
  if(lane == 0) red[w] = v;
  __syncthreads();
  if(w == 0){
    int s = (lane < 8) ? red[lane] : 0;
    #pragma unroll
    for(int o=4;o;o>>=1) s += __shfl_xor_sync(0xffffffffu, s, o);
    if(lane == 0) red[0] = s;
  }
  __syncthreads();
  int poff = red[0];
  int i = b*256 + t;
  int r = g_rowptr[i] + poff;
  g_rowptr[i] = r;
  g_cursor[i] = r;
  if(i == 0) g_rowptr[NN] = NE;
}
__global__ void fill_kernel(const int* __restrict__ src, const int* __restrict__ dst){
  int e = blockIdx.x*blockDim.x + threadIdx.x;
  if(e >= NE) return;
  int s = src[e], d = dst[e];
  int pos = atomicAdd(&g_cursor[d], 1);
  g_edge[pos] = make_float2(__int_as_float(s), g_dis[s]*g_dis[d]);
}

// ======== aggregation (warp/node; edge prefetch + shfl bcast; tf32-rounded output) ========
__global__ void agg64_kernel(const float* __restrict__ hin, float* __restrict__ out){
  int gw = (blockIdx.x*blockDim.x + threadIdx.x) >> 5;
  int lane = threadIdx.x & 31;
  if(gw >= NN) return;
  float2 a = *((const float2*)(hin + (size_t)gw*INDIM) + lane);
  float sn = g_selfn[gw];
  a.x *= sn; a.y *= sn;
  int beg = g_rowptr[gw], end = g_rowptr[gw+1];
  for(int b = beg; b < end; b += 32){
    int m = min(32, end - b);
    float2 myed = make_float2(0.f, 0.f);
    if(lane < m) myed = g_edge[b + lane];
    #pragma unroll 4
    for(int i = 0; i < m; i++){
      int   s = __shfl_sync(0xffffffffu, __float_as_int(myed.x), i);
      float w = __shfl_sync(0xffffffffu, myed.y, i);
      float2 v = *((const float2*)(hin + (size_t)s*INDIM) + lane);
      a.x += w*v.x; a.y += w*v.y;
    }
  }
  *((uint2*)(out + (size_t)gw*INDIM) + lane) = make_uint2(f2tf32(a.x), f2tf32(a.y));
}
__global__ void agg128_kernel(const float* __restrict__ hin, float* __restrict__ out){
  int gw = (blockIdx.x*blockDim.x + threadIdx.x) >> 5;
  int lane = threadIdx.x & 31;
  if(gw >= NN) return;
  float4 a = *((const float4*)(hin + (size_t)gw*HIDD) + lane);
  float sn = g_selfn[gw];
  a.x *= sn; a.y *= sn; a.z *= sn; a.w *= sn;
  int beg = g_rowptr[gw], end = g_rowptr[gw+1];
  for(int b = beg; b < end; b += 32){
    int m = min(32, end - b);
    float2 myed = make_float2(0.f, 0.f);
    if(lane < m) myed = g_edge[b + lane];
    #pragma unroll 4
    for(int i = 0; i < m; i++){
      int   s = __shfl_sync(0xffffffffu, __float_as_int(myed.x), i);
      float w = __shfl_sync(0xffffffffu, myed.y, i);
      float4 v = *((const float4*)(hin + (size_t)s*HIDD) + lane);
      a.x += w*v.x; a.y += w*v.y; a.z += w*v.z; a.w += w*v.w;
    }
  }
  *((uint4*)(out + (size_t)gw*HIDD) + lane) = q4(a);
}

// ========== tf32 mma.sync GEMM: cp.async double-buffered, CK=32, 2 CTAs/SM ==========
template<int BT, int EPI, int KK, int POOL, int RND>
__global__ __launch_bounds__(256, 2)
void gemm_mma_kernel(const float* __restrict__ A, const uint32_t* __restrict__ B,
                     const float* __restrict__ bias,
                     const float* __restrict__ bng, const float* __restrict__ bnb,
                     const float* __restrict__ bnm, const float* __restrict__ bnv,
                     float* __restrict__ C, int Ndt, float* __restrict__ emb)
{
  constexpr int CK  = 32;
  constexpr int NCH = KK / CK;
  constexpr int SA  = 36;
  constexpr int SBN = 132;
  constexpr int BUFA = 128*SA;
  constexpr int BUF  = 2*BUFA;
  extern __shared__ uint32_t sm[];
  const int tid = threadIdx.x;
  const int lane = tid & 31, wid = tid >> 5;
  const int row0 = blockIdx.x * 128;
  const int col0 = blockIdx.y * 128;
  const uint32_t* Ag = (const uint32_t*)A;

  const int m0 = (wid >> 1) * 32;
  const int n0 = (wid & 1) * 64;
  const int g  = lane >> 2;
  const int t4 = lane & 3;

  float acc[2][8][4];
  #pragma unroll
  for(int i=0;i<2;i++)
    #pragma unroll
    for(int j=0;j<8;j++)
      #pragma unroll
      for(int q=0;q<4;q++) acc[i][j][q]=0.f;

  auto stage = [&](int ch){
    const int kbase = ch*CK;
    uint32_t* As = sm + (ch & 1)*BUF;
    uint32_t* Bs = As + BUFA;
    #pragma unroll
    for(int i = 0; i < 4; i++){
      int idx = tid + i*256;
      int r = idx >> 3, q = idx & 7;
      cp16(As + r*SA + q*4, Ag + (size_t)(row0 + r)*KK + kbase + q*4);
    }
    if(BT){
      #pragma unroll
      for(int i = 0; i < 4; i++){
        int idx = tid + i*256;
        int r = idx >> 3, q = idx & 7;
        cp16(Bs + r*SA + q*4, B + (size_t)(col0 + r)*KK + kbase + q*4);
      }
    } else {
      #pragma unroll
      for(int i = 0; i < 4; i++){
        int idx = tid + i*256;
        int k = idx >> 5, n4 = idx & 31;
        cp16(Bs + k*SBN + n4*4, B + (size_t)(kbase + k)*Ndt + col0 + n4*4);
      }
    }
    CP_COMMIT();
  };

  stage(0);

  #pragma unroll 1
  for(int ch = 0; ch < NCH; ch++){
    if(ch + 1 < NCH) stage(ch + 1);
    if(ch + 1 < NCH) asm volatile("cp.async.wait_group 1;" ::: "memory");
    else             asm volatile("cp.async.wait_group 0;" ::: "memory");
    __syncthreads();

    uint32_t* As = sm + (ch & 1)*BUF;
    uint32_t* Bs = As + BUFA;
    const uint32_t* Aw0 = As + (m0 + g)*SA + t4;
    const uint32_t* Aw1 = As + (m0 + 16 + g)*SA + t4;
    const uint32_t* Bw1 = Bs + (n0 + g)*SA + t4;
    const uint32_t* Bw0 = Bs + t4*SBN + n0 + g;

    #pragma unroll 1
    for(int ks = 0; ks < CK/8; ks++){
      const int k0 = ks*8;
      uint32_t af[2][4];
      af[0][0] = Aw0[k0];       af[0][1] = Aw0[8*SA + k0];
      af[0][2] = Aw0[k0 + 4];   af[0][3] = Aw0[8*SA + k0 + 4];
      af[1][0] = Aw1[k0];       af[1][1] = Aw1[8*SA + k0];
      af[1][2] = Aw1[k0 + 4];   af[1][3] = Aw1[8*SA + k0 + 4];
      #pragma unroll
      for(int nj = 0; nj < 8; nj++){
        uint32_t b0, b1;
        if(BT){
          b0 = Bw1[nj*8*SA + k0];
          b1 = Bw1[nj*8*SA + k0 + 4];
        } else {
          b0 = Bw0[k0*SBN + nj*8];
          b1 = Bw0[(k0+4)*SBN + nj*8];
        }
        mma_tf32(acc[0][nj][0], acc[0][nj][1], acc[0][nj][2], acc[0][nj][3],
                 af[0][0], af[0][1], af[0][2], af[0][3], b0, b1);
        mma_tf32(acc[1][nj][0], acc[1][nj][1], acc[1][nj][2], acc[1][nj][3],
                 af[1][0], af[1][1], af[1][2], af[1][3], b0, b1);
      }
    }
    if(ch + 1 < NCH) __syncthreads();
  }

  float cs[8][2];
  if(POOL){
    #pragma unroll
    for(int nj=0;nj<8;nj++){ cs[nj][0]=0.f; cs[nj][1]=0.f; }
  }

  #pragma unroll
  for(int mi = 0; mi < 2; mi++){
    #pragma unroll
    for(int nj = 0; nj < 8; nj++){
      int c = col0 + n0 + nj*8 + t4*2;
      float s0, s1;
      if(EPI){
        s0 = bng[c  ]*rsqrtf(bnv[c  ] + BN_EPS);
        s1 = bng[c+1]*rsqrtf(bnv[c+1] + BN_EPS);
      }
      #pragma unroll
      for(int h = 0; h < 2; h++){
        int r = row0 + m0 + mi*16 + g + h*8;
        float v0 = acc[mi][nj][h*2+0] + bias[c];
        float v1 = acc[mi][nj][h*2+1] + bias[c+1];
        if(EPI){
          v0 = fmaxf((v0 - bnm[c  ])*s0 + bnb[c  ], 0.f);
          v1 = fmaxf((v1 - bnm[c+1])*s1 + bnb[c+1], 0.f);
        }
        if(POOL){ cs[nj][0] += v0; cs[nj][1] += v1; }
        if(RND){
          *(uint2*)(C + (size_t)r*Ndt + c) = make_uint2(f2tf32(v0), f2tf32(v1));
        } else {
          *(float2*)(C + (size_t)r*Ndt + c) = make_float2(v0, v1);
        }
      }
    }
  }

  if(POOL){
    int graph = row0 >> 9;
    #pragma unroll
    for(int nj = 0; nj < 8; nj++){
      float s0 = cs[nj][0], s1 = cs[nj][1];
      #pragma unroll
      for(int o = 4; o <= 16; o <<= 1){
        s0 += __shfl_xor_sync(0xffffffffu, s0, o);
        s1 += __shfl_xor_sync(0xffffffffu, s1, o);
      }
      if(g == 0){
        int c = col0 + n0 + nj*8 + t4*2;
        atomicAdd(&emb[graph*HIDD + c],   s0*(1.0f/PN));
        atomicAdd(&emb[graph*HIDD + c+1], s1*(1.0f/PN));
      }
    }
  }
}

// ================= attention via tf32 mma: CTA per (graph, head, half) ===========
// qkv pre-rounded tf32; Q tiles double-buffered via cp.async; first 64 CTAs zero emb.
#define KSTR 36
#define VSTR 40
#define SSTR 516
#define QSTR 36
#define KS_OFF 0
#define VS_OFF (512*KSTR)
#define S_OFF  (VS_OFF + 512*VSTR)
#define Q_OFF  (S_OFF + 32*SSTR)
#define SINV_OFF (Q_OFF + 2*32*QSTR)
#define ATTN_FLOATS (SINV_OFF + 32)

__global__ __launch_bounds__(256)
void attn_mma_kernel(const float* __restrict__ qkv, float* __restrict__ out,
                     float* __restrict__ emb){
  extern __shared__ float smf[];
  float* S    = smf + S_OFF;
  float* Sinv = smf + SINV_OFF;
  uint32_t* Ku = (uint32_t*)(smf + KS_OFF);
  uint32_t* Vu = (uint32_t*)(smf + VS_OFF);
  uint32_t* Su = (uint32_t*)S;
  uint32_t* Qu = (uint32_t*)(smf + Q_OFF);

  int g    = blockIdx.x >> 3;
  int hd   = (blockIdx.x >> 1) & 3;
  int half = blockIdx.x & 1;
  int n0 = g*PN;
  int t = threadIdx.x;
  int lane = t & 31, warp = t >> 5;
  int gq = lane >> 2, t4 = lane & 3;
  const float scale = 0.17677669529663687f;   // 1/sqrt(32), folded into exp

  // zero emb for the fused pool in the out-proj GEMM (this kernel precedes it)
  if(blockIdx.x < 64) emb[blockIdx.x*256 + t] = 0.f;

  // prefetch Q tile for qi8 (double buffer) — one cp16 per thread
  auto stageQ = [&](int qi8){
    int qt = half*8 + qi8;
    uint32_t* Qb = Qu + (qi8 & 1)*(32*QSTR);
    int r = t >> 3, d4 = (t & 7)*4;
    cp16(Qb + r*QSTR + d4,
         (const uint32_t*)qkv + (size_t)(n0 + qt*32 + r)*384 + hd*32 + d4);
    CP_COMMIT();
  };

  stageQ(0);

  for(int idx = t; idx < PN*8; idx += 256){
    int r = idx >> 3, d4 = (idx & 7)*4;
    const uint32_t* row = (const uint32_t*)qkv + (size_t)(n0 + r)*384 + hd*32;
    *(uint4*)(Ku + r*KSTR + d4) = *(const uint4*)(row + 128 + d4);
    *(uint4*)(Vu + r*VSTR + d4) = *(const uint4*)(row + 256 + d4);
  }

  for(int qi8 = 0; qi8 < 8; qi8++){
    int qt = half*8 + qi8;
    if(qi8 + 1 < 8){
      stageQ(qi8 + 1);
      asm volatile("cp.async.wait_group 1;" ::: "memory");
    } else {
      asm volatile("cp.async.wait_group 0;" ::: "memory");
    }
    __syncthreads();
    const uint32_t* Qb = Qu + (qi8 & 1)*(32*QSTR);

    // Phase A: S = Q K^T (unscaled)
    {
      float c[2][8][4];
      #pragma unroll
      for(int i=0;i<2;i++)
        #pragma unroll
        for(int j=0;j<8;j++)
          #pragma unroll
          for(int q=0;q<4;q++) c[i][j][q]=0.f;

      #pragma unroll 1
      for(int ks = 0; ks < 4; ks++){
        int k0 = ks*8;
        uint32_t a[2][4];
        #pragma unroll
        for(int mi=0;mi<2;mi++){
          const uint32_t* qb = Qb + (mi*16+gq)*QSTR + k0 + t4;
          a[mi][0]=qb[0]; a[mi][1]=qb[8*QSTR]; a[mi][2]=qb[4]; a[mi][3]=qb[8*QSTR+4];
        }
        #pragma unroll
        for(int nj=0;nj<8;nj++){
          const uint32_t* kb = Ku + (warp*64+nj*8+gq)*KSTR + k0 + t4;
          uint32_t b0 = kb[0], b1 = kb[4];
          mma_tf32(c[0][nj][0],c[0][nj][1],c[0][nj][2],c[0][nj][3],
                   a[0][0],a[0][1],a[0][2],a[0][3], b0,b1);
          mma_tf32(c[1][nj][0],c[1][nj][1],c[1][nj][2],c[1][nj][3],
                   a[1][0],a[1][1],a[1][2],a[1][3], b0,b1);
        }
      }
      #pragma unroll
      for(int mi=0;mi<2;mi++)
        #pragma unroll
        for(int nj=0;nj<8;nj++){
          float* sp = S + (mi*16+gq)*SSTR + warp*64 + nj*8 + t4*2;
          *(float2*)(sp)          = make_float2(c[mi][nj][0], c[mi][nj][1]);
          *(float2*)(sp + 8*SSTR) = make_float2(c[mi][nj][2], c[mi][nj][3]);
        }
    }
    __syncthreads();

    // Phase B: exp(s*scale) + sum (float4); normalization deferred
    for(int rr = 0; rr < 4; rr++){
      int r = warp*4 + rr;
      float sum = 0.f;
      float* Srow = S + r*SSTR;
      #pragma unroll
      for(int jj = 0; jj < 4; jj++){
        int j4 = (jj*32 + lane)*4;
        float4 v = *(float4*)(Srow + j4);
        v.x = __expf(v.x*scale); v.y = __expf(v.y*scale);
        v.z = __expf(v.z*scale); v.w = __expf(v.w*scale);
        sum += v.x + v.y + v.z + v.w;
        *(uint4*)((uint32_t*)Srow + j4) = q4(v);
      }
      #pragma unroll
      for(int o=16;o;o>>=1) sum += __shfl_xor_sync(0xffffffffu, sum, o);
      if(lane == 0) Sinv[r] = 1.f/sum;
    }
    __syncthreads();

    // Phase C: O = (E V) * Sinv; output rounded (feeds final GEMM)
    {
      int mi = warp & 1, ni = warp >> 1;
      float c0=0.f,c1=0.f,c2=0.f,c3=0.f;
      const uint32_t* pbase = Su + (mi*16+gq)*SSTR + t4;
      const uint32_t* vbase = Vu + t4*VSTR + ni*8 + gq;
      #pragma unroll 4
      for(int ks = 0; ks < 64; ks++){
        int k0 = ks*8;
        uint32_t a0 = pbase[k0], a1 = pbase[8*SSTR + k0];
        uint32_t a2 = pbase[k0+4], a3 = pbase[8*SSTR + k0+4];
        uint32_t b0 = vbase[k0*VSTR], b1 = vbase[(k0+4)*VSTR];
        mma_tf32(c0,c1,c2,c3, a0,a1,a2,a3, b0,b1);
      }
      int r0 = mi*16 + gq;
      float inv0 = Sinv[r0], inv1 = Sinv[r0+8];
      float* ob = out + (size_t)(n0 + qt*32)*HIDD + hd*32 + ni*8 + t4*2;
      *(uint2*)(ob + (size_t)r0*HIDD)     = make_uint2(f2tf32(c0*inv0), f2tf32(c1*inv0));
      *(uint2*)(ob + (size_t)(r0+8)*HIDD) = make_uint2(f2tf32(c2*inv1), f2tf32(c3*inv1));
    }
    __syncthreads();
  }
}

// ================= launch =================
extern "C" void kernel_launch(void* const* d_in, const int* in_sizes, int n_in,
                              void* d_out, int out_size) {
  const float* x   = (const float*)d_in[0];
  const float* W0  = (const float*)d_in[1];
  const float* b0  = (const float*)d_in[2];
  const float* Wh  = (const float*)d_in[3];
  const float* bh  = (const float*)d_in[4];
  const float* bng = (const float*)d_in[5];
  const float* bnb = (const float*)d_in[6];
  const float* bnm = (const float*)d_in[7];
  const float* bnv = (const float*)d_in[8];
  const float* aiw = (const float*)d_in[9];
  const float* aib = (const float*)d_in[10];
  const float* aow = (const float*)d_in[11];
  const float* aob = (const float*)d_in[12];
  const int*  eidx = (const int*)d_in[13];

  float* out_final = (float*)d_out;
  float* out_emb   = out_final + (size_t)NN*HIDD;

  const int* src = eidx;
  const int* dst = eidx + NE;

  float *p_h, *p_agg, *p_qkv, *p_attno;
  uint32_t* p_wr;
  cudaGetSymbolAddress((void**)&p_h,     g_h);
  cudaGetSymbolAddress((void**)&p_agg,   g_agg);
  cudaGetSymbolAddress((void**)&p_qkv,   g_qkv);
  cudaGetSymbolAddress((void**)&p_attno, g_attno);
  cudaGetSymbolAddress((void**)&p_wr,    g_wr);

  const int GEMM_SMEM = 2*9216*4;         // 73728
  const int ATTN_SMEM = ATTN_FLOATS*4;    // 231040
  cudaFuncSetAttribute(gemm_mma_kernel<0,1,64,0,1>,  cudaFuncAttributeMaxDynamicSharedMemorySize, GEMM_SMEM);
  cudaFuncSetAttribute(gemm_mma_kernel<0,1,128,0,1>, cudaFuncAttributeMaxDynamicSharedMemorySize, GEMM_SMEM);
  cudaFuncSetAttribute(gemm_mma_kernel<1,0,128,0,1>, cudaFuncAttributeMaxDynamicSharedMemorySize, GEMM_SMEM);
  cudaFuncSetAttribute(gemm_mma_kernel<1,0,128,1,0>, cudaFuncAttributeMaxDynamicSharedMemorySize, GEMM_SMEM);
  cudaFuncSetAttribute(attn_mma_kernel,              cudaFuncAttributeMaxDynamicSharedMemorySize, ATTN_SMEM);

  // weight pre-round + count zeroing (one launch)
  roundw_kernel<<<376, 256>>>(W0, Wh, aiw, aow);

  // CSR build
  count_kernel<<<NE/256, 256>>>(dst);
  scan1_kernel<<<256, 256>>>();
  scan23_kernel<<<256, 256>>>();
  fill_kernel<<<NE/256, 256>>>(src, dst);

  // layer 0
  agg64_kernel<<<NN*32/256, 256>>>(x, p_agg);
  gemm_mma_kernel<0,1,64,0,1><<<dim3(512,1), 256, GEMM_SMEM>>>(
      p_agg, p_wr, b0, bng, bnb, bnm, bnv, p_h, 128, nullptr);

  // layers 1..3
  for(int l = 0; l < 3; l++){
    agg128_kernel<<<NN*32/256, 256>>>(p_h, p_agg);
    gemm_mma_kernel<0,1,128,0,1><<<dim3(512,1), 256, GEMM_SMEM>>>(
        p_agg, p_wr + 8192 + l*16384, bh + l*HIDD,
        bng + (l+1)*HIDD, bnb + (l+1)*HIDD, bnm + (l+1)*HIDD, bnv + (l+1)*HIDD,
        p_h, 128, nullptr);
  }

  // qkv projection (output rounded for attention)
  gemm_mma_kernel<1,0,128,0,1><<<dim3(512,3), 256, GEMM_SMEM>>>(
      p_h, p_wr + 57344, aib, nullptr, nullptr, nullptr, nullptr, p_qkv, 384, nullptr);

  // attention (also zeroes out_emb for the fused pool)
  attn_mma_kernel<<<NG*4*2, 256, ATTN_SMEM>>>(p_qkv, p_attno, out_emb);

  // output projection + fused mean pool (unrounded terminal output)
  gemm_mma_kernel<1,0,128,1,0><<<dim3(512,1), 256, GEMM_SMEM>>>(
      p_attno, p_wr + 106496, aob, nullptr, nullptr, nullptr, nullptr, out_final, 128, out_emb);
}

// round 17
// speedup vs baseline: 1.3790x; 1.0741x over previous
#include <cuda_runtime.h>
#include <cstdint>

#define NN 65536
#define NE (NN*16)
#define NG 128
#define PN 512
#define HIDD 128
#define INDIM 64
#define BN_EPS 1e-5f

__device__ __forceinline__ uint32_t f2tf32(float f){
  uint32_t u; asm("cvt.rna.tf32.f32 %0, %1;" : "=r"(u) : "f"(f)); return u;
}
__device__ __forceinline__ void mma_tf32(float& c0, float& c1, float& c2, float& c3,
                                         uint32_t a0, uint32_t a1, uint32_t a2, uint32_t a3,
                                         uint32_t b0, uint32_t b1){
  asm volatile("mma.sync.aligned.m16n8k8.row.col.f32.tf32.tf32.f32 "
               "{%0,%1,%2,%3}, {%4,%5,%6,%7}, {%8,%9}, {%0,%1,%2,%3};"
               : "+f"(c0), "+f"(c1), "+f"(c2), "+f"(c3)
               : "r"(a0), "r"(a1), "r"(a2), "r"(a3), "r"(b0), "r"(b1));
}
__device__ __forceinline__ uint4 q4(float4 v){
  return make_uint4(f2tf32(v.x), f2tf32(v.y), f2tf32(v.z), f2tf32(v.w));
}
__device__ __forceinline__ void cp16(uint32_t* dst, const uint32_t* src){
  uint32_t d = (uint32_t)__cvta_generic_to_shared(dst);
  asm volatile("cp.async.cg.shared.global [%0], [%1], 16;" :: "r"(d), "l"(src));
}
#define CP_COMMIT() asm volatile("cp.async.commit_group;" ::: "memory")

// ================= scratch =================
__device__ int    g_count[NN];
__device__ int    g_rowptr[NN+1];
__device__ int    g_cursor[NN];
__device__ int    g_part[256];
__device__ float2 g_edge[NE];     // (src bits, weight)
__device__ float  g_dis[NN];
__device__ float  g_selfn[NN];
__device__ float  g_h[(size_t)NN*HIDD];
__device__ float  g_agg[(size_t)NN*HIDD];
__device__ float  g_qkv[(size_t)NN*3*HIDD];
__device__ float  g_attno[(size_t)NN*HIDD];
__device__ uint32_t g_wr[122880];   // pre-rounded weights: W0|Wh|aiw|aow

// ============ weight pre-round (tf32) + count zeroing (blocks >= 120) ============
__global__ void roundw_kernel(const float* __restrict__ W0, const float* __restrict__ Wh,
                              const float* __restrict__ aiw, const float* __restrict__ aow){
  int b = blockIdx.x;
  if(b >= 120){
    g_count[(b - 120)*256 + threadIdx.x] = 0;
    return;
  }
  int i = (b*256 + threadIdx.x)*4;
  float4 v;
  if(i < 8192)        v = *(const float4*)(W0 + i);
  else if(i < 57344)  v = *(const float4*)(Wh + (i - 8192));
  else if(i < 106496) v = *(const float4*)(aiw + (i - 57344));
  else                v = *(const float4*)(aow + (i - 106496));
  *(uint4*)(g_wr + i) = q4(v);
}

// ================= CSR build =================
__global__ void count_kernel(const int* __restrict__ dst){
  int e = blockIdx.x*blockDim.x + threadIdx.x;
  if(e < NE) atomicAdd(&g_count[dst[e]], 1);
}
__global__ void scan1_kernel(){
  __shared__ int wsum[8];
  int b = blockIdx.x, t = threadIdx.x;
  int i = b*256 + t;
  int c = g_count[i];
  float dis = rsqrtf((float)(c + 1));
  g_dis[i] = dis;
  g_selfn[i] = dis*dis;
  int lane = t & 31, w = t >> 5;
  int v = c;
  #pragma unroll
  for(int o=1;o<32;o<<=1){ int u=__shfl_up_sync(0xffffffffu,v,o); if(lane>=o) v+=u; }
  if(lane==31) wsum[w]=v;
  __syncthreads();
  if(w==0){
    int s = (lane<8)? wsum[lane] : 0;
    #pragma unroll
    for(int o=1;o<8;o<<=1){ int u=__shfl_up_sync(0xffffffffu,s,o); if(lane>=o) s+=u; }
    if(lane<8) wsum[lane]=s;
  }
  __syncthreads();
  int excl = v - c + (w ? wsum[w-1] : 0);
  g_rowptr[i] = excl;
  if(t==255) g_part[b] = excl + c;
}
// merged scan2+scan3
__global__ void scan23_kernel(){
  __shared__ int red[8];
  int b = blockIdx.x, t = threadIdx.x;
  int lane = t & 31, w = t >> 5;
  int v = (t < b) ? g_part[t] : 0;
  #pragma unroll
  for(int o=16;o;o>>=1) v += __shfl_xor_sync(0xffffffffu, v, o);
  if(lane == 0) red[w] = v;
  __syncthreads();
  if(w == 0){
    int s = (lane < 8) ? red[lane] : 0;
    #pragma unroll
    for(int o=4;o;o>>=1) s += __shfl_xor_sync(0xffffffffu, s, o);
    if(lane == 0) red[0] = s;
  }
  __syncthreads();
  int poff = red[0];
  int i = b*256 + t;
  int r = g_rowptr[i] + poff;
  g_rowptr[i] = r;
  g_cursor[i] = r;
  if(i == 0) g_rowptr[NN] = NE;
}
__global__ void fill_kernel(const int* __restrict__ src, const int* __restrict__ dst){
  int e = blockIdx.x*blockDim.x + threadIdx.x;
  if(e >= NE) return;
  int s = src[e], d = dst[e];
  int pos = atomicAdd(&g_cursor[d], 1);
  g_edge[pos] = make_float2(__int_as_float(s), g_dis[s]*g_dis[d]);
}

// ======== aggregation (warp/node; edge prefetch + shfl bcast; tf32-rounded output) ========
__global__ void agg64_kernel(const float* __restrict__ hin, float* __restrict__ out){
  int gw = (blockIdx.x*blockDim.x + threadIdx.x) >> 5;
  int lane = threadIdx.x & 31;
  if(gw >= NN) return;
  float2 a = *((const float2*)(hin + (size_t)gw*INDIM) + lane);
  float sn = g_selfn[gw];
  a.x *= sn; a.y *= sn;
  int beg = g_rowptr[gw], end = g_rowptr[gw+1];
  for(int b = beg; b < end; b += 32){
    int m = min(32, end - b);
    float2 myed = make_float2(0.f, 0.f);
    if(lane < m) myed = g_edge[b + lane];
    #pragma unroll 4
    for(int i = 0; i < m; i++){
      int   s = __shfl_sync(0xffffffffu, __float_as_int(myed.x), i);
      float w = __shfl_sync(0xffffffffu, myed.y, i);
      float2 v = *((const float2*)(hin + (size_t)s*INDIM) + lane);
      a.x += w*v.x; a.y += w*v.y;
    }
  }
  *((uint2*)(out + (size_t)gw*INDIM) + lane) = make_uint2(f2tf32(a.x), f2tf32(a.y));
}
__global__ void agg128_kernel(const float* __restrict__ hin, float* __restrict__ out){
  int gw = (blockIdx.x*blockDim.x + threadIdx.x) >> 5;
  int lane = threadIdx.x & 31;
  if(gw >= NN) return;
  float4 a = *((const float4*)(hin + (size_t)gw*HIDD) + lane);
  float sn = g_selfn[gw];
  a.x *= sn; a.y *= sn; a.z *= sn; a.w *= sn;
  int beg = g_rowptr[gw], end = g_rowptr[gw+1];
  for(int b = beg; b < end; b += 32){
    int m = min(32, end - b);
    float2 myed = make_float2(0.f, 0.f);
    if(lane < m) myed = g_edge[b + lane];
    #pragma unroll 4
    for(int i = 0; i < m; i++){
      int   s = __shfl_sync(0xffffffffu, __float_as_int(myed.x), i);
      float w = __shfl_sync(0xffffffffu, myed.y, i);
      float4 v = *((const float4*)(hin + (size_t)s*HIDD) + lane);
      a.x += w*v.x; a.y += w*v.y; a.z += w*v.z; a.w += w*v.w;
    }
  }
  *((uint4*)(out + (size_t)gw*HIDD) + lane) = q4(a);
}

// ========== tf32 mma.sync GEMM: cp.async double-buffered, CK=32, 2 CTAs/SM ==========
template<int BT, int EPI, int KK, int POOL, int RND>
__global__ __launch_bounds__(256, 2)
void gemm_mma_kernel(const float* __restrict__ A, const uint32_t* __restrict__ B,
                     const float* __restrict__ bias,
                     const float* __restrict__ bng, const float* __restrict__ bnb,
                     const float* __restrict__ bnm, const float* __restrict__ bnv,
                     float* __restrict__ C, int Ndt, float* __restrict__ emb)
{
  constexpr int CK  = 32;
  constexpr int NCH = KK / CK;
  constexpr int SA  = 36;
  constexpr int SBN = 132;
  constexpr int BUFA = 128*SA;
  constexpr int BUF  = 2*BUFA;
  extern __shared__ uint32_t sm[];
  const int tid = threadIdx.x;
  const int lane = tid & 31, wid = tid >> 5;
  const int row0 = blockIdx.x * 128;
  const int col0 = blockIdx.y * 128;
  const uint32_t* Ag = (const uint32_t*)A;

  const int m0 = (wid >> 1) * 32;
  const int n0 = (wid & 1) * 64;
  const int g  = lane >> 2;
  const int t4 = lane & 3;

  float acc[2][8][4];
  #pragma unroll
  for(int i=0;i<2;i++)
    #pragma unroll
    for(int j=0;j<8;j++)
      #pragma unroll
      for(int q=0;q<4;q++) acc[i][j][q]=0.f;

  auto stage = [&](int ch){
    const int kbase = ch*CK;
    uint32_t* As = sm + (ch & 1)*BUF;
    uint32_t* Bs = As + BUFA;
    #pragma unroll
    for(int i = 0; i < 4; i++){
      int idx = tid + i*256;
      int r = idx >> 3, q = idx & 7;
      cp16(As + r*SA + q*4, Ag + (size_t)(row0 + r)*KK + kbase + q*4);
    }
    if(BT){
      #pragma unroll
      for(int i = 0; i < 4; i++){
        int idx = tid + i*256;
        int r = idx >> 3, q = idx & 7;
        cp16(Bs + r*SA + q*4, B + (size_t)(col0 + r)*KK + kbase + q*4);
      }
    } else {
      #pragma unroll
      for(int i = 0; i < 4; i++){
        int idx = tid + i*256;
        int k = idx >> 5, n4 = idx & 31;
        cp16(Bs + k*SBN + n4*4, B + (size_t)(kbase + k)*Ndt + col0 + n4*4);
      }
    }
    CP_COMMIT();
  };

  stage(0);

  #pragma unroll 1
  for(int ch = 0; ch < NCH; ch++){
    if(ch + 1 < NCH) stage(ch + 1);
    if(ch + 1 < NCH) asm volatile("cp.async.wait_group 1;" ::: "memory");
    else             asm volatile("cp.async.wait_group 0;" ::: "memory");
    __syncthreads();

    uint32_t* As = sm + (ch & 1)*BUF;
    uint32_t* Bs = As + BUFA;
    const uint32_t* Aw0 = As + (m0 + g)*SA + t4;
    const uint32_t* Aw1 = As + (m0 + 16 + g)*SA + t4;
    const uint32_t* Bw1 = Bs + (n0 + g)*SA + t4;
    const uint32_t* Bw0 = Bs + t4*SBN + n0 + g;

    #pragma unroll 1
    for(int ks = 0; ks < CK/8; ks++){
      const int k0 = ks*8;
      uint32_t af[2][4];
      af[0][0] = Aw0[k0];       af[0][1] = Aw0[8*SA + k0];
      af[0][2] = Aw0[k0 + 4];   af[0][3] = Aw0[8*SA + k0 + 4];
      af[1][0] = Aw1[k0];       af[1][1] = Aw1[8*SA + k0];
      af[1][2] = Aw1[k0 + 4];   af[1][3] = Aw1[8*SA + k0 + 4];
      #pragma unroll
      for(int nj = 0; nj < 8; nj++){
        uint32_t b0, b1;
        if(BT){
          b0 = Bw1[nj*8*SA + k0];
          b1 = Bw1[nj*8*SA + k0 + 4];
        } else {
          b0 = Bw0[k0*SBN + nj*8];
          b1 = Bw0[(k0+4)*SBN + nj*8];
        }
        mma_tf32(acc[0][nj][0], acc[0][nj][1], acc[0][nj][2], acc[0][nj][3],
                 af[0][0], af[0][1], af[0][2], af[0][3], b0, b1);
        mma_tf32(acc[1][nj][0], acc[1][nj][1], acc[1][nj][2], acc[1][nj][3],
                 af[1][0], af[1][1], af[1][2], af[1][3], b0, b1);
      }
    }
    if(ch + 1 < NCH) __syncthreads();
  }

  float cs[8][2];
  if(POOL){
    #pragma unroll
    for(int nj=0;nj<8;nj++){ cs[nj][0]=0.f; cs[nj][1]=0.f; }
  }

  #pragma unroll
  for(int mi = 0; mi < 2; mi++){
    #pragma unroll
    for(int nj = 0; nj < 8; nj++){
      int c = col0 + n0 + nj*8 + t4*2;
      float s0, s1;
      if(EPI){
        s0 = bng[c  ]*rsqrtf(bnv[c  ] + BN_EPS);
        s1 = bng[c+1]*rsqrtf(bnv[c+1] + BN_EPS);
      }
      #pragma unroll
      for(int h = 0; h < 2; h++){
        int r = row0 + m0 + mi*16 + g + h*8;
        float v0 = acc[mi][nj][h*2+0] + bias[c];
        float v1 = acc[mi][nj][h*2+1] + bias[c+1];
        if(EPI){
          v0 = fmaxf((v0 - bnm[c  ])*s0 + bnb[c  ], 0.f);
          v1 = fmaxf((v1 - bnm[c+1])*s1 + bnb[c+1], 0.f);
        }
        if(POOL){ cs[nj][0] += v0; cs[nj][1] += v1; }
        if(RND){
          *(uint2*)(C + (size_t)r*Ndt + c) = make_uint2(f2tf32(v0), f2tf32(v1));
        } else {
          *(float2*)(C + (size_t)r*Ndt + c) = make_float2(v0, v1);
        }
      }
    }
  }

  if(POOL){
    int graph = row0 >> 9;
    #pragma unroll
    for(int nj = 0; nj < 8; nj++){
      float s0 = cs[nj][0], s1 = cs[nj][1];
      #pragma unroll
      for(int o = 4; o <= 16; o <<= 1){
        s0 += __shfl_xor_sync(0xffffffffu, s0, o);
        s1 += __shfl_xor_sync(0xffffffffu, s1, o);
      }
      if(g == 0){
        int c = col0 + n0 + nj*8 + t4*2;
        atomicAdd(&emb[graph*HIDD + c],   s0*(1.0f/PN));
        atomicAdd(&emb[graph*HIDD + c+1], s1*(1.0f/PN));
      }
    }
  }
}

// ================= attention via tf32 mma: CTA per (graph, head, half) ===========
// qkv pre-rounded tf32; K/V and Q tiles staged via cp.async; first 64 CTAs zero emb.
#define KSTR 36
#define VSTR 40
#define SSTR 516
#define QSTR 36
#define KS_OFF 0
#define VS_OFF (512*KSTR)
#define S_OFF  (VS_OFF + 512*VSTR)
#define Q_OFF  (S_OFF + 32*SSTR)
#define SINV_OFF (Q_OFF + 2*32*QSTR)
#define ATTN_FLOATS (SINV_OFF + 32)

__global__ __launch_bounds__(256)
void attn_mma_kernel(const float* __restrict__ qkv, float* __restrict__ out,
                     float* __restrict__ emb){
  extern __shared__ float smf[];
  float* S    = smf + S_OFF;
  float* Sinv = smf + SINV_OFF;
  uint32_t* Ku = (uint32_t*)(smf + KS_OFF);
  uint32_t* Vu = (uint32_t*)(smf + VS_OFF);
  uint32_t* Su = (uint32_t*)S;
  uint32_t* Qu = (uint32_t*)(smf + Q_OFF);

  int g    = blockIdx.x >> 3;
  int hd   = (blockIdx.x >> 1) & 3;
  int half = blockIdx.x & 1;
  int n0 = g*PN;
  int t = threadIdx.x;
  int lane = t & 31, warp = t >> 5;
  int gq = lane >> 2, t4 = lane & 3;
  const float scl2 = 0.25500526963693767f;   // (1/sqrt(32)) * log2(e), folded into exp2

  // prefetch Q tile for qi8 (double buffer) — one cp16 per thread
  auto stageQ = [&](int qi8){
    int qt = half*8 + qi8;
    uint32_t* Qb = Qu + (qi8 & 1)*(32*QSTR);
    int r = t >> 3, d4 = (t & 7)*4;
    cp16(Qb + r*QSTR + d4,
         (const uint32_t*)qkv + (size_t)(n0 + qt*32 + r)*384 + hd*32 + d4);
    CP_COMMIT();
  };

  stageQ(0);

  // K/V staging via cp.async (fire-and-forget; drained by first wait_group)
  {
    const uint32_t* base = (const uint32_t*)qkv + (size_t)n0*384 + hd*32;
    for(int idx = t; idx < PN*8; idx += 256){
      int r = idx >> 3, d4 = (idx & 7)*4;
      const uint32_t* row = base + (size_t)r*384;
      cp16(Ku + r*KSTR + d4, row + 128 + d4);
      cp16(Vu + r*VSTR + d4, row + 256 + d4);
    }
    CP_COMMIT();
  }

  // zero emb for the fused pool in the out-proj GEMM (this kernel precedes it)
  if(blockIdx.x < 64) emb[blockIdx.x*256 + t] = 0.f;

  for(int qi8 = 0; qi8 < 8; qi8++){
    int qt = half*8 + qi8;
    if(qi8 + 1 < 8){
      stageQ(qi8 + 1);
      asm volatile("cp.async.wait_group 1;" ::: "memory");
    } else {
      asm volatile("cp.async.wait_group 0;" ::: "memory");
    }
    __syncthreads();
    const uint32_t* Qb = Qu + (qi8 & 1)*(32*QSTR);

    // Phase A: S = Q K^T (unscaled)
    {
      float c[2][8][4];
      #pragma unroll
      for(int i=0;i<2;i++)
        #pragma unroll
        for(int j=0;j<8;j++)
          #pragma unroll
          for(int q=0;q<4;q++) c[i][j][q]=0.f;

      #pragma unroll 1
      for(int ks = 0; ks < 4; ks++){
        int k0 = ks*8;
        uint32_t a[2][4];
        #pragma unroll
        for(int mi=0;mi<2;mi++){
          const uint32_t* qb = Qb + (mi*16+gq)*QSTR + k0 + t4;
          a[mi][0]=qb[0]; a[mi][1]=qb[8*QSTR]; a[mi][2]=qb[4]; a[mi][3]=qb[8*QSTR+4];
        }
        #pragma unroll
        for(int nj=0;nj<8;nj++){
          const uint32_t* kb = Ku + (warp*64+nj*8+gq)*KSTR + k0 + t4;
          uint32_t b0 = kb[0], b1 = kb[4];
          mma_tf32(c[0][nj][0],c[0][nj][1],c[0][nj][2],c[0][nj][3],
                   a[0][0],a[0][1],a[0][2],a[0][3], b0,b1);
          mma_tf32(c[1][nj][0],c[1][nj][1],c[1][nj][2],c[1][nj][3],
                   a[1][0],a[1][1],a[1][2],a[1][3], b0,b1);
        }
      }
      #pragma unroll
      for(int mi=0;mi<2;mi++)
        #pragma unroll
        for(int nj=0;nj<8;nj++){
          float* sp = S + (mi*16+gq)*SSTR + warp*64 + nj*8 + t4*2;
          *(float2*)(sp)          = make_float2(c[mi][nj][0], c[mi][nj][1]);
          *(float2*)(sp + 8*SSTR) = make_float2(c[mi][nj][2], c[mi][nj][3]);
        }
    }
    __syncthreads();

    // Phase B: exp2(s*scl2) + sum (float4); normalization deferred
    for(int rr = 0; rr < 4; rr++){
      int r = warp*4 + rr;
      float sum = 0.f;
      float* Srow = S + r*SSTR;
      #pragma unroll
      for(int jj = 0; jj < 4; jj++){
        int j4 = (jj*32 + lane)*4;
        float4 v = *(float4*)(Srow + j4);
        v.x = exp2f(v.x*scl2); v.y = exp2f(v.y*scl2);
        v.z = exp2f(v.z*scl2); v.w = exp2f(v.w*scl2);
        sum += v.x + v.y + v.z + v.w;
        *(uint4*)((uint32_t*)Srow + j4) = q4(v);
      }
      #pragma unroll
      for(int o=16;o;o>>=1) sum += __shfl_xor_sync(0xffffffffu, sum, o);
      if(lane == 0) Sinv[r] = 1.f/sum;
    }
    __syncthreads();

    // Phase C: O = (E V) * Sinv; output rounded (feeds final GEMM)
    {
      int mi = warp & 1, ni = warp >> 1;
      float c0=0.f,c1=0.f,c2=0.f,c3=0.f;
      const uint32_t* pbase = Su + (mi*16+gq)*SSTR + t4;
      const uint32_t* vbase = Vu + t4*VSTR + ni*8 + gq;
      #pragma unroll 4
      for(int ks = 0; ks < 64; ks++){
        int k0 = ks*8;
        uint32_t a0 = pbase[k0], a1 = pbase[8*SSTR + k0];
        uint32_t a2 = pbase[k0+4], a3 = pbase[8*SSTR + k0+4];
        uint32_t b0 = vbase[k0*VSTR], b1 = vbase[(k0+4)*VSTR];
        mma_tf32(c0,c1,c2,c3, a0,a1,a2,a3, b0,b1);
      }
      int r0 = mi*16 + gq;
      float inv0 = Sinv[r0], inv1 = Sinv[r0+8];
      float* ob = out + (size_t)(n0 + qt*32)*HIDD + hd*32 + ni*8 + t4*2;
      *(uint2*)(ob + (size_t)r0*HIDD)     = make_uint2(f2tf32(c0*inv0), f2tf32(c1*inv0));
      *(uint2*)(ob + (size_t)(r0+8)*HIDD) = make_uint2(f2tf32(c2*inv1), f2tf32(c3*inv1));
    }
    __syncthreads();
  }
}

// ================= launch =================
extern "C" void kernel_launch(void* const* d_in, const int* in_sizes, int n_in,
                              void* d_out, int out_size) {
  const float* x   = (const float*)d_in[0];
  const float* W0  = (const float*)d_in[1];
  const float* b0  = (const float*)d_in[2];
  const float* Wh  = (const float*)d_in[3];
  const float* bh  = (const float*)d_in[4];
  const float* bng = (const float*)d_in[5];
  const float* bnb = (const float*)d_in[6];
  const float* bnm = (const float*)d_in[7];
  const float* bnv = (const float*)d_in[8];
  const float* aiw = (const float*)d_in[9];
  const float* aib = (const float*)d_in[10];
  const float* aow = (const float*)d_in[11];
  const float* aob = (const float*)d_in[12];
  const int*  eidx = (const int*)d_in[13];

  float* out_final = (float*)d_out;
  float* out_emb   = out_final + (size_t)NN*HIDD;

  const int* src = eidx;
  const int* dst = eidx + NE;

  float *p_h, *p_agg, *p_qkv, *p_attno;
  uint32_t* p_wr;
  cudaGetSymbolAddress((void**)&p_h,     g_h);
  cudaGetSymbolAddress((void**)&p_agg,   g_agg);
  cudaGetSymbolAddress((void**)&p_qkv,   g_qkv);
  cudaGetSymbolAddress((void**)&p_attno, g_attno);
  cudaGetSymbolAddress((void**)&p_wr,    g_wr);

  const int GEMM_SMEM = 2*9216*4;         // 73728
  const int ATTN_SMEM = ATTN_FLOATS*4;    // 231040
  cudaFuncSetAttribute(gemm_mma_kernel<0,1,64,0,1>,  cudaFuncAttributeMaxDynamicSharedMemorySize, GEMM_SMEM);
  cudaFuncSetAttribute(gemm_mma_kernel<0,1,128,0,1>, cudaFuncAttributeMaxDynamicSharedMemorySize, GEMM_SMEM);
  cudaFuncSetAttribute(gemm_mma_kernel<1,0,128,0,1>, cudaFuncAttributeMaxDynamicSharedMemorySize, GEMM_SMEM);
  cudaFuncSetAttribute(gemm_mma_kernel<1,0,128,1,0>, cudaFuncAttributeMaxDynamicSharedMemorySize, GEMM_SMEM);
  cudaFuncSetAttribute(attn_mma_kernel,              cudaFuncAttributeMaxDynamicSharedMemorySize, ATTN_SMEM);

  // weight pre-round + count zeroing (one launch)
  roundw_kernel<<<376, 256>>>(W0, Wh, aiw, aow);

  // CSR build
  count_kernel<<<NE/256, 256>>>(dst);
  scan1_kernel<<<256, 256>>>();
  scan23_kernel<<<256, 256>>>();
  fill_kernel<<<NE/256, 256>>>(src, dst);

  // layer 0
  agg64_kernel<<<NN*32/256, 256>>>(x, p_agg);
  gemm_mma_kernel<0,1,64,0,1><<<dim3(512,1), 256, GEMM_SMEM>>>(
      p_agg, p_wr, b0, bng, bnb, bnm, bnv, p_h, 128, nullptr);

  // layers 1..3
  for(int l = 0; l < 3; l++){
    agg128_kernel<<<NN*32/256, 256>>>(p_h, p_agg);
    gemm_mma_kernel<0,1,128,0,1><<<dim3(512,1), 256, GEMM_SMEM>>>(
        p_agg, p_wr + 8192 + l*16384, bh + l*HIDD,
        bng + (l+1)*HIDD, bnb + (l+1)*HIDD, bnm + (l+1)*HIDD, bnv + (l+1)*HIDD,
        p_h, 128, nullptr);
  }

  // qkv projection (output rounded for attention)
  gemm_mma_kernel<1,0,128,0,1><<<dim3(512,3), 256, GEMM_SMEM>>>(
      p_h, p_wr + 57344, aib, nullptr, nullptr, nullptr, nullptr, p_qkv, 384, nullptr);

  // attention (also zeroes out_emb for the fused pool)
  attn_mma_kernel<<<NG*4*2, 256, ATTN_SMEM>>>(p_qkv, p_attno, out_emb);

  // output projection + fused mean pool (unrounded terminal output)
  gemm_mma_kernel<1,0,128,1,0><<<dim3(512,1), 256, GEMM_SMEM>>>(
      p_attno, p_wr + 106496, aob, nullptr, nullptr, nullptr, nullptr, out_final, 128, out_emb);
}